// round 9
// baseline (speedup 1.0000x reference)
#include <cuda_runtime.h>
#include <math.h>

#define BB 32
#define HH 256
#define LL 2048
#define NS 64
#define FF 32
#define BHL (BB*HH*LL)

typedef unsigned long long u64;

// ---------------- f32x2 helpers ----------------
__device__ __forceinline__ u64 pk2(float lo, float hi) {
    u64 r; asm("mov.b64 %0, {%1, %2};" : "=l"(r) : "f"(lo), "f"(hi)); return r;
}
__device__ __forceinline__ void up2(u64 v, float& a, float& b) {
    asm("mov.b64 {%0, %1}, %2;" : "=f"(a), "=f"(b) : "l"(v));
}
__device__ __forceinline__ u64 fma2(u64 a, u64 b, u64 c) {
    u64 d; asm("fma.rn.f32x2 %0, %1, %2, %3;" : "=l"(d) : "l"(a), "l"(b), "l"(c)); return d;
}
__device__ __forceinline__ u64 mul2(u64 a, u64 b) {
    u64 d; asm("mul.rn.f32x2 %0, %1, %2;" : "=l"(d) : "l"(a), "l"(b)); return d;
}

__device__ __forceinline__ float gatef(float o) {
    float u = __expf(fminf(-o, 25.f));
    float u2 = u * u;
    return (1.f - u2) / ((1.f + u2) * (1.f + u));
}
__device__ __forceinline__ float geluf(float y) {
    float u = 0.7978845608028654f * fmaf(0.044715f*y, y*y, y);
    float e = __expf(fminf(-2.f*u, 80.f));
    float th = (1.f - e) / (1.f + e);
    return 0.5f*y*(1.f + th);
}

// ---------------- scratch ----------------
__device__ float g_tb[BB*HH];
__device__ float g_wr[HH*NS], g_wi[HH*NS];
__device__ float g_c0r[HH*NS], g_c0i[HH*NS], g_c1r[HH*NS], g_c1i[HH*NS];
__device__ float g_z [BHL];
__device__ float g_yf[BHL];   // fwd scan out; after ticket: gelu(yf + yb + D*z)
__device__ float g_yb[BHL];   // bwd scan out (+ D*z folded)
__device__ int   g_cnt[BB*HH];

// ---------------- zero tickets ----------------
__global__ void k_zero()
{
    g_cnt[blockIdx.x*256 + threadIdx.x] = 0;
}

// ---------------- t @ Wt^T + bt ----------------
__global__ void k_tb(const float* __restrict__ t, const float* __restrict__ Wt,
                     const float* __restrict__ bt)
{
    __shared__ float ts[HH];
    int b = blockIdx.x, h = threadIdx.x;
    ts[h] = t[b*HH + h];
    __syncthreads();
    float acc = bt[h];
    const float* wrow = Wt + (size_t)h*HH;
    #pragma unroll 8
    for (int k = 0; k < HH; k++) acc = fmaf(ts[k], wrow[k], acc);
    g_tb[b*HH + h] = acc;
}

// ---------------- SSM parameter prep ----------------
__global__ void k_ssm(const float* __restrict__ log_dt, const float* __restrict__ logA_real,
                      const float* __restrict__ A_imag, const float* __restrict__ C_re,
                      const float* __restrict__ C_im)
{
    int i = blockIdx.x*blockDim.x + threadIdx.x;
    if (i >= HH*NS) return;
    int h = i / NS;
    float dt = expf(log_dt[h]);
    float Ar = -expf(logA_real[i]);
    float Ai = A_imag[i];
    float dr = dt*Ar, di = dt*Ai;
    float er = expf(dr);
    float wr = er*cosf(di), wi = er*sinf(di);
    g_wr[i] = wr; g_wi[i] = wi;
    float Er = wr - 1.0f, Ei = wi;
    float inv = 1.0f/(Ar*Ar + Ai*Ai);
    float qr = (Er*Ar + Ei*Ai)*inv;
    float qi = (Ei*Ar - Er*Ai)*inv;
    {
        float cr = C_re[i], ci = C_im[i];
        g_c0r[i] = 2.0f*(cr*qr - ci*qi);
        g_c0i[i] = 2.0f*(cr*qi + ci*qr);
    }
    {
        float cr = C_re[HH*NS + i], ci = C_im[HH*NS + i];
        g_c1r[i] = 2.0f*(cr*qr - ci*qi);
        g_c1i[i] = 2.0f*(cr*qi + ci*qr);
    }
}

// ---------------- LayerNorm over H -> z ----------------
__global__ void k_ln(const float* __restrict__ x, const float* __restrict__ ln_g,
                     const float* __restrict__ ln_b)
{
    __shared__ float tbs[HH], gs[HH], bs[HH];
    int b = blockIdx.y;
    int l = blockIdx.x*256 + threadIdx.x;
    tbs[threadIdx.x] = g_tb[b*HH + threadIdx.x];
    gs[threadIdx.x]  = ln_g[threadIdx.x];
    bs[threadIdx.x]  = ln_b[threadIdx.x];
    __syncthreads();
    const float* xb = x + (size_t)b*HH*LL + l;
    float s = 0.f, ss = 0.f;
    #pragma unroll 8
    for (int h = 0; h < HH; h++) {
        float v = xb[(size_t)h*LL] + tbs[h];
        s += v; ss = fmaf(v, v, ss);
    }
    float mu  = s * (1.0f/HH);
    float var = ss*(1.0f/HH) - mu*mu;
    float rstd = rsqrtf(var + 1e-5f);
    float* zb = g_z + (size_t)b*HH*LL + l;
    #pragma unroll 8
    for (int h = 0; h < HH; h++) {
        float v = xb[(size_t)h*LL] + tbs[h];
        zb[(size_t)h*LL] = (v - mu)*rstd*gs[h] + bs[h];
    }
}

// ---------------- scan: 16-row transpose buf, single-wave residency, gelu ticket ----------------
#define SCAN_WPB 4
__global__ void __launch_bounds__(32*SCAN_WPB, 14) k_scan(const float* __restrict__ Dv)
{
    __shared__ __align__(16) float pbuf[SCAN_WPB][16*33];
    __shared__ __align__(16) u64   zbuf[SCAN_WPB][32];
    int wid  = threadIdx.x >> 5;
    int lane = threadIdx.x & 31;
    int gw   = blockIdx.x*SCAN_WPB + wid;   // 0 .. 2*B*H-1
    int bh   = gw >> 1;
    int dir  = gw & 1;
    int h    = bh & (HH-1);
    int ci   = h*NS + lane;
    float* pw = pbuf[wid];
    u64*   zw = zbuf[wid];
    const float* zwf = (const float*)zw;   // packed (z,z): low word at index 2*j
    const int row = lane & 15;
    const int k0  = (lane >> 4) * 16;

    u64 wr2  = pk2(g_wr[ci],  g_wr[ci+32]);
    u64 wi2  = pk2(g_wi[ci],  g_wi[ci+32]);
    u64 wi2n = pk2(-g_wi[ci], -g_wi[ci+32]);
    u64 cr2, ci2n;
    if (dir == 0) { cr2 = pk2(g_c0r[ci], g_c0r[ci+32]); ci2n = pk2(-g_c0i[ci], -g_c0i[ci+32]); }
    else          { cr2 = pk2(g_c1r[ci], g_c1r[ci+32]); ci2n = pk2(-g_c1i[ci], -g_c1i[ci+32]); }

    const float* zp = g_z + (size_t)bh*LL;
    float* yp = (dir == 0 ? g_yf : g_yb) + (size_t)bh*LL;

    u64 sr = 0ULL, si = 0ULL;

    if (dir == 0) {
        for (int t = 0; t < LL/32; t++) {
            int l0 = t*32;
            float zv = zp[l0 + lane];
            zw[lane] = pk2(zv, zv);
            __syncwarp();
            // subtile 0: j = 0..15
            #pragma unroll
            for (int j = 0; j < 16; j++) {
                u64 z2  = zw[j];
                u64 nsr = fma2(wr2, sr, fma2(wi2n, si, z2));
                si = fma2(wr2, si, mul2(wi2, sr));
                sr = nsr;
                u64 p2 = fma2(cr2, sr, mul2(ci2n, si));
                float pa, pb; up2(p2, pa, pb);
                pw[j*33 + lane] = pa + pb;
            }
            __syncwarp();
            {
                float acc = 0.f;
                #pragma unroll
                for (int k = 0; k < 16; k++) acc += pw[row*33 + k0 + k];
                acc += __shfl_xor_sync(0xffffffffu, acc, 16);
                if (lane < 16) yp[l0 + row] = acc;
            }
            __syncwarp();
            // subtile 1: j = 16..31
            #pragma unroll
            for (int j = 16; j < 32; j++) {
                u64 z2  = zw[j];
                u64 nsr = fma2(wr2, sr, fma2(wi2n, si, z2));
                si = fma2(wr2, si, mul2(wi2, sr));
                sr = nsr;
                u64 p2 = fma2(cr2, sr, mul2(ci2n, si));
                float pa, pb; up2(p2, pa, pb);
                pw[(j-16)*33 + lane] = pa + pb;
            }
            __syncwarp();
            {
                float acc = 0.f;
                #pragma unroll
                for (int k = 0; k < 16; k++) acc += pw[row*33 + k0 + k];
                acc += __shfl_xor_sync(0xffffffffu, acc, 16);
                if (lane < 16) yp[l0 + 16 + row] = acc;
            }
            __syncwarp();
        }
    } else {
        float d = Dv[h];
        for (int t = 0; t < LL/32; t++) {
            int l0 = LL - 32*(t+1);
            float zv = zp[l0 + lane];
            zw[lane] = pk2(zv, zv);
            __syncwarp();
            // subtile 0: j = 31..16 (emit from state BEFORE absorbing z[l0+j])
            #pragma unroll
            for (int jj = 0; jj < 16; jj++) {
                int j = 31 - jj;
                u64 p2 = fma2(cr2, sr, mul2(ci2n, si));
                float pa, pb; up2(p2, pa, pb);
                pw[(j-16)*33 + lane] = pa + pb;
                u64 z2  = zw[j];
                u64 nsr = fma2(wr2, sr, fma2(wi2n, si, z2));
                si = fma2(wr2, si, mul2(wi2, sr));
                sr = nsr;
            }
            __syncwarp();
            {
                float acc = 0.f;
                #pragma unroll
                for (int k = 0; k < 16; k++) acc += pw[row*33 + k0 + k];
                acc += __shfl_xor_sync(0xffffffffu, acc, 16);
                if (lane < 16) {
                    float zj = zwf[(16 + row)*2];
                    yp[l0 + 16 + row] = fmaf(d, zj, acc);   // fold D*z
                }
            }
            __syncwarp();
            // subtile 1: j = 15..0
            #pragma unroll
            for (int jj = 0; jj < 16; jj++) {
                int j = 15 - jj;
                u64 p2 = fma2(cr2, sr, mul2(ci2n, si));
                float pa, pb; up2(p2, pa, pb);
                pw[j*33 + lane] = pa + pb;
                u64 z2  = zw[j];
                u64 nsr = fma2(wr2, sr, fma2(wi2n, si, z2));
                si = fma2(wr2, si, mul2(wi2, sr));
                sr = nsr;
            }
            __syncwarp();
            {
                float acc = 0.f;
                #pragma unroll
                for (int k = 0; k < 16; k++) acc += pw[row*33 + k0 + k];
                acc += __shfl_xor_sync(0xffffffffu, acc, 16);
                if (lane < 16) {
                    float zj = zwf[row*2];
                    yp[l0 + row] = fmaf(d, zj, acc);        // fold D*z
                }
            }
            __syncwarp();
        }
    }

    // ---- ticket: second finisher for this (b,h) row applies gelu(yf+yb) -> g_yf ----
    __threadfence();
    int old = 0;
    if (lane == 0) old = atomicAdd(&g_cnt[bh], 1);
    old = __shfl_sync(0xffffffffu, old, 0);
    if (old == 1) {
        __threadfence();
        const float4* fa = (const float4*)(g_yf + (size_t)bh*LL);
        const float4* fb = (const float4*)(g_yb + (size_t)bh*LL);
        float4*       fo = (float4*)      (g_yf + (size_t)bh*LL);
        #pragma unroll
        for (int i = lane; i < LL/4; i += 32) {
            float4 a = fa[i], b = fb[i];
            float4 o;
            o.x = geluf(a.x + b.x);
            o.y = geluf(a.y + b.y);
            o.z = geluf(a.z + b.z);
            o.w = geluf(a.w + b.w);
            fo[i] = o;
        }
    }
}

// ---------------- stage1: 128x64 tile ----------------
__global__ __launch_bounds__(256) void k_stage1(const float* __restrict__ Wout, const float* __restrict__ bout,
                         const float* __restrict__ x, const float* __restrict__ feat,
                         const float* __restrict__ Wf, const float* __restrict__ bf)
{
    __shared__ __align__(16) float Ws[16][130];
    __shared__ __align__(16) float Bs[16][65];
    const int b  = blockIdx.z;
    const int g0 = blockIdx.y * 128;
    const int l0 = blockIdx.x * 64;
    const int tid = threadIdx.x;
    const int tx = tid & 15, ty = tid >> 4;
    const int arow = tid >> 1, akg = (tid & 1) * 8;
    const int brow = tid >> 4, bc0 = tid & 15;

    u64 acc[4][4];
    #pragma unroll
    for (int r = 0; r < 4; r++)
        #pragma unroll
        for (int j = 0; j < 4; j++) acc[r][j] = 0ULL;

    const float* act = g_yf + (size_t)b*HH*LL;
    for (int k0 = 0; k0 < HH; k0 += 16) {
        float4 w0 = *(const float4*)(Wout + (size_t)(g0+arow)*HH + k0 + akg);
        float4 w1 = *(const float4*)(Wout + (size_t)(g0+arow)*HH + k0 + akg + 4);
        Ws[akg+0][arow]=w0.x; Ws[akg+1][arow]=w0.y; Ws[akg+2][arow]=w0.z; Ws[akg+3][arow]=w0.w;
        Ws[akg+4][arow]=w1.x; Ws[akg+5][arow]=w1.y; Ws[akg+6][arow]=w1.z; Ws[akg+7][arow]=w1.w;
        #pragma unroll
        for (int c = 0; c < 4; c++)
            Bs[brow][bc0 + 16*c] = act[(size_t)(k0+brow)*LL + l0 + bc0 + 16*c];
        __syncthreads();
        #pragma unroll
        for (int k = 0; k < 16; k++) {
            u64 ap[4], bp[4];
            #pragma unroll
            for (int r = 0; r < 4; r++) ap[r] = *(const u64*)&Ws[k][ty*8 + 2*r];
            #pragma unroll
            for (int j = 0; j < 4; j++) { float v = Bs[k][16*j + tx]; bp[j] = pk2(v, v); }
            #pragma unroll
            for (int r = 0; r < 4; r++)
                #pragma unroll
                for (int j = 0; j < 4; j++)
                    acc[r][j] = fma2(ap[r], bp[j], acc[r][j]);
        }
        __syncthreads();
    }
    const float* fb = feat + (size_t)b*FF*LL;
    for (int k0 = 0; k0 < FF; k0 += 16) {
        float4 w0 = *(const float4*)(Wf + (size_t)(g0+arow)*FF + k0 + akg);
        float4 w1 = *(const float4*)(Wf + (size_t)(g0+arow)*FF + k0 + akg + 4);
        Ws[akg+0][arow]=w0.x; Ws[akg+1][arow]=w0.y; Ws[akg+2][arow]=w0.z; Ws[akg+3][arow]=w0.w;
        Ws[akg+4][arow]=w1.x; Ws[akg+5][arow]=w1.y; Ws[akg+6][arow]=w1.z; Ws[akg+7][arow]=w1.w;
        #pragma unroll
        for (int c = 0; c < 4; c++)
            Bs[brow][bc0 + 16*c] = fb[(size_t)(k0+brow)*LL + l0 + bc0 + 16*c];
        __syncthreads();
        #pragma unroll
        for (int k = 0; k < 16; k++) {
            u64 ap[4], bp[4];
            #pragma unroll
            for (int r = 0; r < 4; r++) ap[r] = *(const u64*)&Ws[k][ty*8 + 2*r];
            #pragma unroll
            for (int j = 0; j < 4; j++) { float v = Bs[k][16*j + tx]; bp[j] = pk2(v, v); }
            #pragma unroll
            for (int r = 0; r < 4; r++)
                #pragma unroll
                for (int j = 0; j < 4; j++)
                    acc[r][j] = fma2(ap[r], bp[j], acc[r][j]);
        }
        __syncthreads();
    }
    float base[8];
    #pragma unroll
    for (int i = 0; i < 8; i++) {
        int g = g0 + ty*8 + i;
        base[i] = bout[g] + bf[g] + g_tb[b*HH + g];
    }
    #pragma unroll
    for (int r = 0; r < 4; r++) {
        int g = g0 + ty*8 + 2*r;
        #pragma unroll
        for (int j = 0; j < 4; j++) {
            float v0, v1; up2(acc[r][j], v0, v1);
            int col = l0 + 16*j + tx;
            size_t off0 = ((size_t)b*HH + g)*LL + col;
            size_t off1 = off0 + LL;
            float o0 = v0 + base[2*r]   + x[off0];
            float o1 = v1 + base[2*r+1] + x[off1];
            g_z[off0] = gatef(o0);
            g_z[off1] = gatef(o1);
        }
    }
}

// ---------------- stage2: o1 = W1@g + b1 + x ; o2 = W2@g + b2 ----------------
__global__ __launch_bounds__(256) void k_stage2(const float* __restrict__ W1, const float* __restrict__ b1,
                         const float* __restrict__ W2, const float* __restrict__ b2,
                         const float* __restrict__ x, float* __restrict__ o1,
                         float* __restrict__ o2)
{
    __shared__ __align__(16) float W1s[16][130];
    __shared__ __align__(16) float W2s[16][130];
    __shared__ __align__(16) float Bs[16][65];
    const int b  = blockIdx.z;
    const int g0 = blockIdx.y * 128;
    const int l0 = blockIdx.x * 64;
    const int tid = threadIdx.x;
    const int tx = tid & 15, ty = tid >> 4;
    const int arow = tid >> 1, akg = (tid & 1) * 8;
    const int brow = tid >> 4, bc0 = tid & 15;

    u64 acc1[4][4], acc2[4][4];
    #pragma unroll
    for (int r = 0; r < 4; r++)
        #pragma unroll
        for (int j = 0; j < 4; j++) { acc1[r][j] = 0ULL; acc2[r][j] = 0ULL; }

    const float* gb = g_z + (size_t)b*HH*LL;
    for (int k0 = 0; k0 < HH; k0 += 16) {
        float4 w0 = *(const float4*)(W1 + (size_t)(g0+arow)*HH + k0 + akg);
        float4 w1 = *(const float4*)(W1 + (size_t)(g0+arow)*HH + k0 + akg + 4);
        W1s[akg+0][arow]=w0.x; W1s[akg+1][arow]=w0.y; W1s[akg+2][arow]=w0.z; W1s[akg+3][arow]=w0.w;
        W1s[akg+4][arow]=w1.x; W1s[akg+5][arow]=w1.y; W1s[akg+6][arow]=w1.z; W1s[akg+7][arow]=w1.w;
        float4 v0 = *(const float4*)(W2 + (size_t)(g0+arow)*HH + k0 + akg);
        float4 v1 = *(const float4*)(W2 + (size_t)(g0+arow)*HH + k0 + akg + 4);
        W2s[akg+0][arow]=v0.x; W2s[akg+1][arow]=v0.y; W2s[akg+2][arow]=v0.z; W2s[akg+3][arow]=v0.w;
        W2s[akg+4][arow]=v1.x; W2s[akg+5][arow]=v1.y; W2s[akg+6][arow]=v1.z; W2s[akg+7][arow]=v1.w;
        #pragma unroll
        for (int c = 0; c < 4; c++)
            Bs[brow][bc0 + 16*c] = gb[(size_t)(k0+brow)*LL + l0 + bc0 + 16*c];
        __syncthreads();
        #pragma unroll
        for (int k = 0; k < 16; k++) {
            u64 a1[4], a2[4], bp[4];
            #pragma unroll
            for (int r = 0; r < 4; r++) a1[r] = *(const u64*)&W1s[k][ty*8 + 2*r];
            #pragma unroll
            for (int r = 0; r < 4; r++) a2[r] = *(const u64*)&W2s[k][ty*8 + 2*r];
            #pragma unroll
            for (int j = 0; j < 4; j++) { float v = Bs[k][16*j + tx]; bp[j] = pk2(v, v); }
            #pragma unroll
            for (int r = 0; r < 4; r++)
                #pragma unroll
                for (int j = 0; j < 4; j++) {
                    acc1[r][j] = fma2(a1[r], bp[j], acc1[r][j]);
                    acc2[r][j] = fma2(a2[r], bp[j], acc2[r][j]);
                }
        }
        __syncthreads();
    }
    #pragma unroll
    for (int r = 0; r < 4; r++) {
        int g = g0 + ty*8 + 2*r;
        float bb1a = b1[g], bb1b = b1[g+1];
        float bb2a = b2[g], bb2b = b2[g+1];
        #pragma unroll
        for (int j = 0; j < 4; j++) {
            int col = l0 + 16*j + tx;
            size_t off0 = ((size_t)b*HH + g)*LL + col;
            size_t off1 = off0 + LL;
            float p0, p1, q0, q1;
            up2(acc1[r][j], p0, p1);
            up2(acc2[r][j], q0, q1);
            o1[off0] = p0 + bb1a + x[off0];
            o1[off1] = p1 + bb1b + x[off1];
            o2[off0] = q0 + bb2a;
            o2[off1] = q1 + bb2b;
        }
    }
}

// ---------------- launch ----------------
extern "C" void kernel_launch(void* const* d_in, const int* in_sizes, int n_in,
                              void* d_out, int out_size)
{
    const float* x        = (const float*)d_in[0];
    const float* t        = (const float*)d_in[1];
    const float* feat     = (const float*)d_in[2];
    const float* Wt       = (const float*)d_in[3];
    const float* bt       = (const float*)d_in[4];
    const float* ln_g     = (const float*)d_in[5];
    const float* ln_b     = (const float*)d_in[6];
    const float* log_dt   = (const float*)d_in[7];
    const float* logA_real= (const float*)d_in[8];
    const float* A_imag   = (const float*)d_in[9];
    const float* C_re     = (const float*)d_in[10];
    const float* C_im     = (const float*)d_in[11];
    const float* Dv       = (const float*)d_in[12];
    const float* Wout     = (const float*)d_in[13];
    const float* bout     = (const float*)d_in[14];
    const float* W1       = (const float*)d_in[15];
    const float* b1       = (const float*)d_in[16];
    const float* W2       = (const float*)d_in[17];
    const float* b2       = (const float*)d_in[18];
    const float* Wf       = (const float*)d_in[19];
    const float* bf       = (const float*)d_in[20];

    float* o1 = (float*)d_out;
    float* o2 = (float*)d_out + (size_t)BHL;

    k_zero<<<(BB*HH)/256, 256>>>();
    k_tb<<<BB, 256>>>(t, Wt, bt);
    k_ssm<<<(HH*NS+255)/256, 256>>>(log_dt, logA_real, A_imag, C_re, C_im);
    k_ln<<<dim3(LL/256, BB), 256>>>(x, ln_g, ln_b);
    k_scan<<<(2*BB*HH)/SCAN_WPB, 32*SCAN_WPB>>>(Dv);
    k_stage1<<<dim3(LL/64, HH/128, BB), 256>>>(Wout, bout, x, feat, Wf, bf);
    k_stage2<<<dim3(LL/64, HH/128, BB), 256>>>(W1, b1, W2, b2, x, o1, o2);
}

// round 10
// speedup vs baseline: 1.3592x; 1.3592x over previous
#include <cuda_runtime.h>
#include <math.h>
#include <stdint.h>

#define BB 32
#define HH 256
#define LL 2048
#define NS 64
#define FF 32
#define BHL (BB*HH*LL)

typedef unsigned long long u64;

// ---------------- f32x2 helpers ----------------
__device__ __forceinline__ u64 pk2(float lo, float hi) {
    u64 r; asm("mov.b64 %0, {%1, %2};" : "=l"(r) : "f"(lo), "f"(hi)); return r;
}
__device__ __forceinline__ void up2(u64 v, float& a, float& b) {
    asm("mov.b64 {%0, %1}, %2;" : "=f"(a), "=f"(b) : "l"(v));
}
__device__ __forceinline__ u64 fma2(u64 a, u64 b, u64 c) {
    u64 d; asm("fma.rn.f32x2 %0, %1, %2, %3;" : "=l"(d) : "l"(a), "l"(b), "l"(c)); return d;
}
__device__ __forceinline__ u64 mul2(u64 a, u64 b) {
    u64 d; asm("mul.rn.f32x2 %0, %1, %2;" : "=l"(d) : "l"(a), "l"(b)); return d;
}

// ---------------- tf32 mma helpers ----------------
__device__ __forceinline__ uint32_t tf32c(float x) {
    uint32_t r; asm("cvt.rna.tf32.f32 %0, %1;" : "=r"(r) : "f"(x)); return r;
}
__device__ __forceinline__ void mma8(float d[4], const uint32_t a[4], const uint32_t b[2]) {
    asm("mma.sync.aligned.m16n8k8.row.col.f32.tf32.tf32.f32 "
        "{%0,%1,%2,%3}, {%4,%5,%6,%7}, {%8,%9}, {%0,%1,%2,%3};"
        : "+f"(d[0]), "+f"(d[1]), "+f"(d[2]), "+f"(d[3])
        : "r"(a[0]), "r"(a[1]), "r"(a[2]), "r"(a[3]), "r"(b[0]), "r"(b[1]));
}

__device__ __forceinline__ float gatef(float o) {
    float u = __expf(fminf(-o, 25.f));
    float u2 = u * u;
    return (1.f - u2) / ((1.f + u2) * (1.f + u));
}
__device__ __forceinline__ float geluf(float y) {
    float u = 0.7978845608028654f * fmaf(0.044715f*y, y*y, y);
    float e = __expf(fminf(-2.f*u, 80.f));
    float th = (1.f - e) / (1.f + e);
    return 0.5f*y*(1.f + th);
}

// ---------------- scratch ----------------
__device__ float g_tb[BB*HH];
__device__ float g_wr[HH*NS], g_wi[HH*NS];
__device__ float g_c0r[HH*NS], g_c0i[HH*NS], g_c1r[HH*NS], g_c1i[HH*NS];
__device__ float g_z [BHL];
__device__ float g_yf[BHL];   // fwd scan out; after ticket: gelu(yf + yb + D*z)
__device__ float g_yb[BHL];   // bwd scan out (+ D*z folded)
__device__ int   g_cnt[BB*HH];

// ---------------- zero tickets ----------------
__global__ void k_zero()
{
    g_cnt[blockIdx.x*256 + threadIdx.x] = 0;
}

// ---------------- t @ Wt^T + bt ----------------
__global__ void k_tb(const float* __restrict__ t, const float* __restrict__ Wt,
                     const float* __restrict__ bt)
{
    __shared__ float ts[HH];
    int b = blockIdx.x, h = threadIdx.x;
    ts[h] = t[b*HH + h];
    __syncthreads();
    float acc = bt[h];
    const float* wrow = Wt + (size_t)h*HH;
    #pragma unroll 8
    for (int k = 0; k < HH; k++) acc = fmaf(ts[k], wrow[k], acc);
    g_tb[b*HH + h] = acc;
}

// ---------------- SSM parameter prep ----------------
__global__ void k_ssm(const float* __restrict__ log_dt, const float* __restrict__ logA_real,
                      const float* __restrict__ A_imag, const float* __restrict__ C_re,
                      const float* __restrict__ C_im)
{
    int i = blockIdx.x*blockDim.x + threadIdx.x;
    if (i >= HH*NS) return;
    int h = i / NS;
    float dt = expf(log_dt[h]);
    float Ar = -expf(logA_real[i]);
    float Ai = A_imag[i];
    float dr = dt*Ar, di = dt*Ai;
    float er = expf(dr);
    float wr = er*cosf(di), wi = er*sinf(di);
    g_wr[i] = wr; g_wi[i] = wi;
    float Er = wr - 1.0f, Ei = wi;
    float inv = 1.0f/(Ar*Ar + Ai*Ai);
    float qr = (Er*Ar + Ei*Ai)*inv;
    float qi = (Ei*Ar - Er*Ai)*inv;
    {
        float cr = C_re[i], ci = C_im[i];
        g_c0r[i] = 2.0f*(cr*qr - ci*qi);
        g_c0i[i] = 2.0f*(cr*qi + ci*qr);
    }
    {
        float cr = C_re[HH*NS + i], ci = C_im[HH*NS + i];
        g_c1r[i] = 2.0f*(cr*qr - ci*qi);
        g_c1i[i] = 2.0f*(cr*qi + ci*qr);
    }
}

// ---------------- LayerNorm over H -> z ----------------
__global__ void k_ln(const float* __restrict__ x, const float* __restrict__ ln_g,
                     const float* __restrict__ ln_b)
{
    __shared__ float tbs[HH], gs[HH], bs[HH];
    int b = blockIdx.y;
    int l = blockIdx.x*256 + threadIdx.x;
    tbs[threadIdx.x] = g_tb[b*HH + threadIdx.x];
    gs[threadIdx.x]  = ln_g[threadIdx.x];
    bs[threadIdx.x]  = ln_b[threadIdx.x];
    __syncthreads();
    const float* xb = x + (size_t)b*HH*LL + l;
    float s = 0.f, ss = 0.f;
    #pragma unroll 8
    for (int h = 0; h < HH; h++) {
        float v = xb[(size_t)h*LL] + tbs[h];
        s += v; ss = fmaf(v, v, ss);
    }
    float mu  = s * (1.0f/HH);
    float var = ss*(1.0f/HH) - mu*mu;
    float rstd = rsqrtf(var + 1e-5f);
    float* zb = g_z + (size_t)b*HH*LL + l;
    #pragma unroll 8
    for (int h = 0; h < HH; h++) {
        float v = xb[(size_t)h*LL] + tbs[h];
        zb[(size_t)h*LL] = (v - mu)*rstd*gs[h] + bs[h];
    }
}

// ---------------- scan (R8 best config) + fused gelu ticket ----------------
#define SCAN_WPB 4
__global__ __launch_bounds__(32*SCAN_WPB) void k_scan(const float* __restrict__ Dv)
{
    __shared__ __align__(16) float pbuf[SCAN_WPB][32*33];
    __shared__ __align__(16) u64   zbuf[SCAN_WPB][32];
    int wid  = threadIdx.x >> 5;
    int lane = threadIdx.x & 31;
    int gw   = blockIdx.x*SCAN_WPB + wid;   // 0 .. 2*B*H-1
    int bh   = gw >> 1;
    int dir  = gw & 1;
    int h    = bh & (HH-1);
    int ci   = h*NS + lane;
    float* pw = pbuf[wid];
    u64*   zw = zbuf[wid];

    u64 wr2  = pk2(g_wr[ci],  g_wr[ci+32]);
    u64 wi2  = pk2(g_wi[ci],  g_wi[ci+32]);
    u64 wi2n = pk2(-g_wi[ci], -g_wi[ci+32]);
    u64 cr2, ci2n;
    if (dir == 0) { cr2 = pk2(g_c0r[ci], g_c0r[ci+32]); ci2n = pk2(-g_c0i[ci], -g_c0i[ci+32]); }
    else          { cr2 = pk2(g_c1r[ci], g_c1r[ci+32]); ci2n = pk2(-g_c1i[ci], -g_c1i[ci+32]); }

    const float* zp = g_z + (size_t)bh*LL;
    float* yp = (dir == 0 ? g_yf : g_yb) + (size_t)bh*LL;

    u64 sr = 0ULL, si = 0ULL;

    if (dir == 0) {
        for (int t = 0; t < LL/32; t++) {
            int l0 = t*32;
            float zv = zp[l0 + lane];
            zw[lane] = pk2(zv, zv);
            __syncwarp();
            #pragma unroll
            for (int j = 0; j < 32; j++) {
                u64 z2  = zw[j];
                u64 nsr = fma2(wr2, sr, fma2(wi2n, si, z2));
                si = fma2(wr2, si, mul2(wi2, sr));
                sr = nsr;
                u64 p2 = fma2(cr2, sr, mul2(ci2n, si));
                float pa, pb; up2(p2, pa, pb);
                pw[j*33 + lane] = pa + pb;
            }
            __syncwarp();
            float acc = 0.f;
            #pragma unroll
            for (int k = 0; k < 32; k++) acc += pw[lane*33 + k];
            yp[l0 + lane] = acc;
            __syncwarp();
        }
    } else {
        float d = Dv[h];
        for (int t = 0; t < LL/32; t++) {
            int l0 = LL - 32*(t+1);
            float zv = zp[l0 + lane];
            zw[lane] = pk2(zv, zv);
            __syncwarp();
            #pragma unroll
            for (int j = 31; j >= 0; j--) {
                // emit contribution from state BEFORE absorbing z[l0+j]
                u64 p2 = fma2(cr2, sr, mul2(ci2n, si));
                float pa, pb; up2(p2, pa, pb);
                pw[j*33 + lane] = pa + pb;
                u64 z2  = zw[j];
                u64 nsr = fma2(wr2, sr, fma2(wi2n, si, z2));
                si = fma2(wr2, si, mul2(wi2, sr));
                sr = nsr;
            }
            __syncwarp();
            float acc = 0.f;
            #pragma unroll
            for (int k = 0; k < 32; k++) acc += pw[lane*33 + k];
            yp[l0 + lane] = fmaf(d, zv, acc);   // fold D*z into bwd output
            __syncwarp();
        }
    }

    // ---- ticket: second finisher for this (b,h) row applies gelu(yf+yb) -> g_yf ----
    __threadfence();
    int old = 0;
    if (lane == 0) old = atomicAdd(&g_cnt[bh], 1);
    old = __shfl_sync(0xffffffffu, old, 0);
    if (old == 1) {
        __threadfence();
        const float4* fa = (const float4*)(g_yf + (size_t)bh*LL);
        const float4* fb = (const float4*)(g_yb + (size_t)bh*LL);
        float4*       fo = (float4*)      (g_yf + (size_t)bh*LL);
        #pragma unroll
        for (int i = lane; i < LL/4; i += 32) {
            float4 a = fa[i], b = fb[i];
            float4 o;
            o.x = geluf(a.x + b.x);
            o.y = geluf(a.y + b.y);
            o.z = geluf(a.z + b.z);
            o.w = geluf(a.w + b.w);
            fo[i] = o;
        }
    }
}

// ================= tf32 tensor-core GEMM stages =================
// Mapping: m = g (output channel), n = l (sequence), k = h.
// A = W[g][h] row-major (m x k). B = Act[h][l] (k x n).
// CTA tile: 128 g x 64 l, K-chunks of 32. 256 threads = 8 warps (4 g x 2 l),
// warp tile 32 g x 32 l = 2 m-frags x 4 n-frags of m16n8k8.
// W smem pitch 36 words (A-frag LDS conflict-free: 4*gr+tc distinct mod 32).
// Act smem pitch 72 words (B-frag LDS conflict-free: 8*tc+gr distinct mod 32).
#define PW 36
#define PB 72

// copy one 128x32 weight chunk (row-major src, stride sk) into smem [g][k] pitch PW, tf32-converted
__device__ __forceinline__ void copy_w_chunk(uint32_t* Ws, const float* __restrict__ W,
                                             int g0, int k0, int sk, int tid)
{
    int g = tid >> 1, h0 = (tid & 1) * 16;
    const float4* src = (const float4*)(W + (size_t)(g0 + g)*sk + k0 + h0);
    uint32_t* dst = Ws + g*PW + h0;
    #pragma unroll
    for (int i = 0; i < 4; i++) {
        float4 v = src[i];
        uint4 u;
        u.x = tf32c(v.x); u.y = tf32c(v.y); u.z = tf32c(v.z); u.w = tf32c(v.w);
        *(uint4*)(dst + 4*i) = u;
    }
}

// copy one 32x64 activation chunk (row-major src, stride LL) into smem [k][l] pitch PB, tf32-converted
__device__ __forceinline__ void copy_b_chunk(uint32_t* Bsm, const float* __restrict__ Act,
                                             int k0, int l0, int tid)
{
    int hh = tid >> 3, lo = (tid & 7) * 8;
    const float4* src = (const float4*)(Act + (size_t)(k0 + hh)*LL + l0 + lo);
    uint32_t* dst = Bsm + hh*PB + lo;
    #pragma unroll
    for (int i = 0; i < 2; i++) {
        float4 v = src[i];
        uint4 u;
        u.x = tf32c(v.x); u.y = tf32c(v.y); u.z = tf32c(v.z); u.w = tf32c(v.w);
        *(uint4*)(dst + 4*i) = u;
    }
}

// run 4 k-steps (one 32-chunk) of mma for one weight smem buffer into d[2][4][4]
__device__ __forceinline__ void mma_chunk(float d[2][4][4], const uint32_t* Ws, const uint32_t* Bsm,
                                          int wg, int wl, int gr, int tc)
{
    #pragma unroll
    for (int ks = 0; ks < 4; ks++) {
        int kk = ks*8;
        uint32_t a[2][4], bb[4][2];
        #pragma unroll
        for (int mi = 0; mi < 2; mi++) {
            const uint32_t* p = Ws + (wg + mi*16 + gr)*PW + kk + tc;
            a[mi][0] = p[0];
            a[mi][1] = p[8*PW];
            a[mi][2] = p[4];
            a[mi][3] = p[8*PW + 4];
        }
        #pragma unroll
        for (int ni = 0; ni < 4; ni++) {
            const uint32_t* p = Bsm + (kk + tc)*PB + wl + ni*8 + gr;
            bb[ni][0] = p[0];
            bb[ni][1] = p[4*PB];
        }
        #pragma unroll
        for (int mi = 0; mi < 2; mi++)
            #pragma unroll
            for (int ni = 0; ni < 4; ni++)
                mma8(d[mi][ni], a[mi], bb[ni]);
    }
}

// ---------------- stage1: g_z = gate(Wout@gelu_y + Wf@feat + bout + bf + tb + x) ----------------
__global__ __launch_bounds__(256) void k_stage1(const float* __restrict__ Wout, const float* __restrict__ bout,
                         const float* __restrict__ x, const float* __restrict__ feat,
                         const float* __restrict__ Wf, const float* __restrict__ bf)
{
    __shared__ uint32_t Ws[128*PW];
    __shared__ uint32_t Bsm[32*PB];
    const int b  = blockIdx.z;
    const int g0 = blockIdx.y * 128;
    const int l0 = blockIdx.x * 64;
    const int tid = threadIdx.x;
    const int w = tid >> 5, lane = tid & 31;
    const int wg = (w >> 1) * 32, wl = (w & 1) * 32;
    const int gr = lane >> 2, tc = lane & 3;

    float d[2][4][4];
    #pragma unroll
    for (int mi = 0; mi < 2; mi++)
        #pragma unroll
        for (int ni = 0; ni < 4; ni++)
            #pragma unroll
            for (int q = 0; q < 4; q++) d[mi][ni][q] = 0.f;

    const float* act = g_yf + (size_t)b*HH*LL;
    for (int c = 0; c < HH/32; c++) {
        int k0 = c*32;
        copy_w_chunk(Ws, Wout, g0, k0, HH, tid);
        copy_b_chunk(Bsm, act, k0, l0, tid);
        __syncthreads();
        mma_chunk(d, Ws, Bsm, wg, wl, gr, tc);
        __syncthreads();
    }
    // feature encoder chunk (K = 32)
    {
        copy_w_chunk(Ws, Wf, g0, 0, FF, tid);
        copy_b_chunk(Bsm, feat + (size_t)b*FF*LL, 0, l0, tid);
        __syncthreads();
        mma_chunk(d, Ws, Bsm, wg, wl, gr, tc);
        __syncthreads();
    }
    // epilogue: + bout + bf + tb + x, gate -> g_z
    #pragma unroll
    for (int mi = 0; mi < 2; mi++) {
        int ga = g0 + wg + mi*16 + gr;
        int gb2 = ga + 8;
        float basea = bout[ga]  + bf[ga]  + g_tb[b*HH + ga];
        float baseb = bout[gb2] + bf[gb2] + g_tb[b*HH + gb2];
        #pragma unroll
        for (int ni = 0; ni < 4; ni++) {
            int l = l0 + wl + ni*8 + 2*tc;
            size_t offa = ((size_t)b*HH + ga)*LL + l;
            size_t offb = ((size_t)b*HH + gb2)*LL + l;
            float2 xa = *(const float2*)(x + offa);
            float2 xb = *(const float2*)(x + offb);
            float2 ra, rb;
            ra.x = gatef(d[mi][ni][0] + basea + xa.x);
            ra.y = gatef(d[mi][ni][1] + basea + xa.y);
            rb.x = gatef(d[mi][ni][2] + baseb + xb.x);
            rb.y = gatef(d[mi][ni][3] + baseb + xb.y);
            *(float2*)(g_z + offa) = ra;
            *(float2*)(g_z + offb) = rb;
        }
    }
}

// ---------------- stage2: o1 = W1@g + b1 + x ; o2 = W2@g + b2 ----------------
__global__ __launch_bounds__(256) void k_stage2(const float* __restrict__ W1, const float* __restrict__ b1,
                         const float* __restrict__ W2, const float* __restrict__ b2,
                         const float* __restrict__ x, float* __restrict__ o1,
                         float* __restrict__ o2)
{
    __shared__ uint32_t W1s[128*PW];
    __shared__ uint32_t W2s[128*PW];
    __shared__ uint32_t Bsm[32*PB];
    const int b  = blockIdx.z;
    const int g0 = blockIdx.y * 128;
    const int l0 = blockIdx.x * 64;
    const int tid = threadIdx.x;
    const int w = tid >> 5, lane = tid & 31;
    const int wg = (w >> 1) * 32, wl = (w & 1) * 32;
    const int gr = lane >> 2, tc = lane & 3;

    float d1[2][4][4], d2[2][4][4];
    #pragma unroll
    for (int mi = 0; mi < 2; mi++)
        #pragma unroll
        for (int ni = 0; ni < 4; ni++)
            #pragma unroll
            for (int q = 0; q < 4; q++) { d1[mi][ni][q] = 0.f; d2[mi][ni][q] = 0.f; }

    const float* gb = g_z + (size_t)b*HH*LL;
    for (int c = 0; c < HH/32; c++) {
        int k0 = c*32;
        copy_w_chunk(W1s, W1, g0, k0, HH, tid);
        copy_w_chunk(W2s, W2, g0, k0, HH, tid);
        copy_b_chunk(Bsm, gb, k0, l0, tid);
        __syncthreads();
        #pragma unroll
        for (int ks = 0; ks < 4; ks++) {
            int kk = ks*8;
            uint32_t a1[2][4], a2[2][4], bb[4][2];
            #pragma unroll
            for (int mi = 0; mi < 2; mi++) {
                const uint32_t* p1 = W1s + (wg + mi*16 + gr)*PW + kk + tc;
                a1[mi][0] = p1[0]; a1[mi][1] = p1[8*PW]; a1[mi][2] = p1[4]; a1[mi][3] = p1[8*PW + 4];
                const uint32_t* p2 = W2s + (wg + mi*16 + gr)*PW + kk + tc;
                a2[mi][0] = p2[0]; a2[mi][1] = p2[8*PW]; a2[mi][2] = p2[4]; a2[mi][3] = p2[8*PW + 4];
            }
            #pragma unroll
            for (int ni = 0; ni < 4; ni++) {
                const uint32_t* p = Bsm + (kk + tc)*PB + wl + ni*8 + gr;
                bb[ni][0] = p[0];
                bb[ni][1] = p[4*PB];
            }
            #pragma unroll
            for (int mi = 0; mi < 2; mi++)
                #pragma unroll
                for (int ni = 0; ni < 4; ni++) {
                    mma8(d1[mi][ni], a1[mi], bb[ni]);
                    mma8(d2[mi][ni], a2[mi], bb[ni]);
                }
        }
        __syncthreads();
    }
    // epilogue
    #pragma unroll
    for (int mi = 0; mi < 2; mi++) {
        int ga = g0 + wg + mi*16 + gr;
        int gb2 = ga + 8;
        float b1a = b1[ga], b1b = b1[gb2];
        float b2a = b2[ga], b2b = b2[gb2];
        #pragma unroll
        for (int ni = 0; ni < 4; ni++) {
            int l = l0 + wl + ni*8 + 2*tc;
            size_t offa = ((size_t)b*HH + ga)*LL + l;
            size_t offb = ((size_t)b*HH + gb2)*LL + l;
            float2 xa = *(const float2*)(x + offa);
            float2 xb = *(const float2*)(x + offb);
            float2 r;
            r.x = d1[mi][ni][0] + b1a + xa.x;
            r.y = d1[mi][ni][1] + b1a + xa.y;
            *(float2*)(o1 + offa) = r;
            r.x = d1[mi][ni][2] + b1b + xb.x;
            r.y = d1[mi][ni][3] + b1b + xb.y;
            *(float2*)(o1 + offb) = r;
            r.x = d2[mi][ni][0] + b2a;
            r.y = d2[mi][ni][1] + b2a;
            *(float2*)(o2 + offa) = r;
            r.x = d2[mi][ni][2] + b2b;
            r.y = d2[mi][ni][3] + b2b;
            *(float2*)(o2 + offb) = r;
        }
    }
}

// ---------------- launch ----------------
extern "C" void kernel_launch(void* const* d_in, const int* in_sizes, int n_in,
                              void* d_out, int out_size)
{
    const float* x        = (const float*)d_in[0];
    const float* t        = (const float*)d_in[1];
    const float* feat     = (const float*)d_in[2];
    const float* Wt       = (const float*)d_in[3];
    const float* bt       = (const float*)d_in[4];
    const float* ln_g     = (const float*)d_in[5];
    const float* ln_b     = (const float*)d_in[6];
    const float* log_dt   = (const float*)d_in[7];
    const float* logA_real= (const float*)d_in[8];
    const float* A_imag   = (const float*)d_in[9];
    const float* C_re     = (const float*)d_in[10];
    const float* C_im     = (const float*)d_in[11];
    const float* Dv       = (const float*)d_in[12];
    const float* Wout     = (const float*)d_in[13];
    const float* bout     = (const float*)d_in[14];
    const float* W1       = (const float*)d_in[15];
    const float* b1       = (const float*)d_in[16];
    const float* W2       = (const float*)d_in[17];
    const float* b2       = (const float*)d_in[18];
    const float* Wf       = (const float*)d_in[19];
    const float* bf       = (const float*)d_in[20];

    float* o1 = (float*)d_out;
    float* o2 = (float*)d_out + (size_t)BHL;

    k_zero<<<(BB*HH)/256, 256>>>();
    k_tb<<<BB, 256>>>(t, Wt, bt);
    k_ssm<<<(HH*NS+255)/256, 256>>>(log_dt, logA_real, A_imag, C_re, C_im);
    k_ln<<<dim3(LL/256, BB), 256>>>(x, ln_g, ln_b);
    k_scan<<<(2*BB*HH)/SCAN_WPB, 32*SCAN_WPB>>>(Dv);
    k_stage1<<<dim3(LL/64, HH/128, BB), 256>>>(Wout, bout, x, feat, Wf, bf);
    k_stage2<<<dim3(LL/64, HH/128, BB), 256>>>(W1, b1, W2, b2, x, o1, o2);
}

// round 11
// speedup vs baseline: 1.3931x; 1.0250x over previous
#include <cuda_runtime.h>
#include <math.h>
#include <stdint.h>

#define BB 32
#define HH 256
#define LL 2048
#define NS 64
#define FF 32
#define BHL (BB*HH*LL)

typedef unsigned long long u64;

// ---------------- f32x2 helpers ----------------
__device__ __forceinline__ u64 pk2(float lo, float hi) {
    u64 r; asm("mov.b64 %0, {%1, %2};" : "=l"(r) : "f"(lo), "f"(hi)); return r;
}
__device__ __forceinline__ void up2(u64 v, float& a, float& b) {
    asm("mov.b64 {%0, %1}, %2;" : "=f"(a), "=f"(b) : "l"(v));
}
__device__ __forceinline__ u64 fma2(u64 a, u64 b, u64 c) {
    u64 d; asm("fma.rn.f32x2 %0, %1, %2, %3;" : "=l"(d) : "l"(a), "l"(b), "l"(c)); return d;
}
__device__ __forceinline__ u64 mul2(u64 a, u64 b) {
    u64 d; asm("mul.rn.f32x2 %0, %1, %2;" : "=l"(d) : "l"(a), "l"(b)); return d;
}

// ---------------- tf32 helpers ----------------
__device__ __forceinline__ uint32_t tf32c(float x) {
    uint32_t r; asm("cvt.rna.tf32.f32 %0, %1;" : "=r"(r) : "f"(x)); return r;
}
__device__ __forceinline__ float rtf(float x) { return __uint_as_float(tf32c(x)); }
__device__ __forceinline__ void mma8(float d[4], const uint32_t a[4], const uint32_t b[2]) {
    asm("mma.sync.aligned.m16n8k8.row.col.f32.tf32.tf32.f32 "
        "{%0,%1,%2,%3}, {%4,%5,%6,%7}, {%8,%9}, {%0,%1,%2,%3};"
        : "+f"(d[0]), "+f"(d[1]), "+f"(d[2]), "+f"(d[3])
        : "r"(a[0]), "r"(a[1]), "r"(a[2]), "r"(a[3]), "r"(b[0]), "r"(b[1]));
}

// ---------------- cp.async helpers ----------------
__device__ __forceinline__ void cpa16(uint32_t s, const float* g) {
    asm volatile("cp.async.cg.shared.global [%0], [%1], 16;" :: "r"(s), "l"(g));
}
__device__ __forceinline__ void cp_commit() { asm volatile("cp.async.commit_group;"); }
__device__ __forceinline__ void cp_wait1()  { asm volatile("cp.async.wait_group 1;"); }
__device__ __forceinline__ void cp_wait0()  { asm volatile("cp.async.wait_group 0;"); }

__device__ __forceinline__ float gatef(float o) {
    float u = __expf(fminf(-o, 25.f));
    float u2 = u * u;
    return (1.f - u2) / ((1.f + u2) * (1.f + u));
}
__device__ __forceinline__ float geluf(float y) {
    float u = 0.7978845608028654f * fmaf(0.044715f*y, y*y, y);
    float e = __expf(fminf(-2.f*u, 80.f));
    float th = (1.f - e) / (1.f + e);
    return 0.5f*y*(1.f + th);
}

// ---------------- scratch ----------------
__device__ float g_tb[BB*HH];
__device__ float g_wr[HH*NS], g_wi[HH*NS];
__device__ float g_c0r[HH*NS], g_c0i[HH*NS], g_c1r[HH*NS], g_c1i[HH*NS];
__device__ float g_z [BHL];
__device__ float g_yf[BHL];   // fwd scan out; after ticket: tf32(gelu(yf+yb+D*z))
__device__ float g_yb[BHL];
__device__ int   g_cnt[BB*HH];
// tf32-pre-rounded GEMM operands
__device__ float g_WoutT[HH*HH], g_W1T[HH*HH], g_W2T[HH*HH], g_WfT[HH*FF];
__device__ float g_ft[BB*FF*LL];

// ---------------- zero tickets ----------------
__global__ void k_zero()
{
    g_cnt[blockIdx.x*256 + threadIdx.x] = 0;
}

// ---------------- pre-round weights / features to tf32 ----------------
__global__ void k_cvtw(const float* __restrict__ Wout, const float* __restrict__ W1,
                       const float* __restrict__ W2, const float* __restrict__ Wf)
{
    int i = blockIdx.x*256 + threadIdx.x;      // 0..65535
    g_WoutT[i] = rtf(Wout[i]);
    g_W1T[i]   = rtf(W1[i]);
    g_W2T[i]   = rtf(W2[i]);
    if (i < HH*FF) g_WfT[i] = rtf(Wf[i]);
}
__global__ void k_cvtf(const float* __restrict__ feat)
{
    int i = blockIdx.x*256 + threadIdx.x;      // 0..BB*FF*LL-1
    g_ft[i] = rtf(feat[i]);
}

// ---------------- t @ Wt^T + bt ----------------
__global__ void k_tb(const float* __restrict__ t, const float* __restrict__ Wt,
                     const float* __restrict__ bt)
{
    __shared__ float ts[HH];
    int b = blockIdx.x, h = threadIdx.x;
    ts[h] = t[b*HH + h];
    __syncthreads();
    float acc = bt[h];
    const float* wrow = Wt + (size_t)h*HH;
    #pragma unroll 8
    for (int k = 0; k < HH; k++) acc = fmaf(ts[k], wrow[k], acc);
    g_tb[b*HH + h] = acc;
}

// ---------------- SSM parameter prep ----------------
__global__ void k_ssm(const float* __restrict__ log_dt, const float* __restrict__ logA_real,
                      const float* __restrict__ A_imag, const float* __restrict__ C_re,
                      const float* __restrict__ C_im)
{
    int i = blockIdx.x*blockDim.x + threadIdx.x;
    if (i >= HH*NS) return;
    int h = i / NS;
    float dt = expf(log_dt[h]);
    float Ar = -expf(logA_real[i]);
    float Ai = A_imag[i];
    float dr = dt*Ar, di = dt*Ai;
    float er = expf(dr);
    float wr = er*cosf(di), wi = er*sinf(di);
    g_wr[i] = wr; g_wi[i] = wi;
    float Er = wr - 1.0f, Ei = wi;
    float inv = 1.0f/(Ar*Ar + Ai*Ai);
    float qr = (Er*Ar + Ei*Ai)*inv;
    float qi = (Ei*Ar - Er*Ai)*inv;
    {
        float cr = C_re[i], ci = C_im[i];
        g_c0r[i] = 2.0f*(cr*qr - ci*qi);
        g_c0i[i] = 2.0f*(cr*qi + ci*qr);
    }
    {
        float cr = C_re[HH*NS + i], ci = C_im[HH*NS + i];
        g_c1r[i] = 2.0f*(cr*qr - ci*qi);
        g_c1i[i] = 2.0f*(cr*qi + ci*qr);
    }
}

// ---------------- LayerNorm over H -> z (4-way h-split for occupancy) ----------------
__global__ void k_ln(const float* __restrict__ x, const float* __restrict__ ln_g,
                     const float* __restrict__ ln_b)
{
    __shared__ float tbs[HH], gs[HH], bs[HH];
    __shared__ float sms[4][64], smss[4][64];
    int b = blockIdx.y;
    int tid = threadIdx.x;
    tbs[tid] = g_tb[b*HH + tid];
    gs[tid]  = ln_g[tid];
    bs[tid]  = ln_b[tid];
    __syncthreads();
    int lg = tid & 63, hg = tid >> 6;
    int l = blockIdx.x*64 + lg;
    const float* xb = x + (size_t)b*HH*LL + l;
    float s = 0.f, ss = 0.f;
    #pragma unroll 8
    for (int h = hg*64; h < hg*64 + 64; h++) {
        float v = xb[(size_t)h*LL] + tbs[h];
        s += v; ss = fmaf(v, v, ss);
    }
    sms[hg][lg] = s; smss[hg][lg] = ss;
    __syncthreads();
    float st  = sms[0][lg]  + sms[1][lg]  + sms[2][lg]  + sms[3][lg];
    float sst = smss[0][lg] + smss[1][lg] + smss[2][lg] + smss[3][lg];
    float mu  = st * (1.0f/HH);
    float var = sst*(1.0f/HH) - mu*mu;
    float rstd = rsqrtf(var + 1e-5f);
    float* zb = g_z + (size_t)b*HH*LL + l;
    #pragma unroll 8
    for (int h = hg*64; h < hg*64 + 64; h++) {
        float v = xb[(size_t)h*LL] + tbs[h];
        zb[(size_t)h*LL] = (v - mu)*rstd*gs[h] + bs[h];
    }
}

// ---------------- scan (R8 best config) + fused gelu ticket (tf32-rounded store) ----------------
#define SCAN_WPB 4
__global__ __launch_bounds__(32*SCAN_WPB) void k_scan(const float* __restrict__ Dv)
{
    __shared__ __align__(16) float pbuf[SCAN_WPB][32*33];
    __shared__ __align__(16) u64   zbuf[SCAN_WPB][32];
    int wid  = threadIdx.x >> 5;
    int lane = threadIdx.x & 31;
    int gw   = blockIdx.x*SCAN_WPB + wid;
    int bh   = gw >> 1;
    int dir  = gw & 1;
    int h    = bh & (HH-1);
    int ci   = h*NS + lane;
    float* pw = pbuf[wid];
    u64*   zw = zbuf[wid];

    u64 wr2  = pk2(g_wr[ci],  g_wr[ci+32]);
    u64 wi2  = pk2(g_wi[ci],  g_wi[ci+32]);
    u64 wi2n = pk2(-g_wi[ci], -g_wi[ci+32]);
    u64 cr2, ci2n;
    if (dir == 0) { cr2 = pk2(g_c0r[ci], g_c0r[ci+32]); ci2n = pk2(-g_c0i[ci], -g_c0i[ci+32]); }
    else          { cr2 = pk2(g_c1r[ci], g_c1r[ci+32]); ci2n = pk2(-g_c1i[ci], -g_c1i[ci+32]); }

    const float* zp = g_z + (size_t)bh*LL;
    float* yp = (dir == 0 ? g_yf : g_yb) + (size_t)bh*LL;

    u64 sr = 0ULL, si = 0ULL;

    if (dir == 0) {
        for (int t = 0; t < LL/32; t++) {
            int l0 = t*32;
            float zv = zp[l0 + lane];
            zw[lane] = pk2(zv, zv);
            __syncwarp();
            #pragma unroll
            for (int j = 0; j < 32; j++) {
                u64 z2  = zw[j];
                u64 nsr = fma2(wr2, sr, fma2(wi2n, si, z2));
                si = fma2(wr2, si, mul2(wi2, sr));
                sr = nsr;
                u64 p2 = fma2(cr2, sr, mul2(ci2n, si));
                float pa, pb; up2(p2, pa, pb);
                pw[j*33 + lane] = pa + pb;
            }
            __syncwarp();
            float acc = 0.f;
            #pragma unroll
            for (int k = 0; k < 32; k++) acc += pw[lane*33 + k];
            yp[l0 + lane] = acc;
            __syncwarp();
        }
    } else {
        float d = Dv[h];
        for (int t = 0; t < LL/32; t++) {
            int l0 = LL - 32*(t+1);
            float zv = zp[l0 + lane];
            zw[lane] = pk2(zv, zv);
            __syncwarp();
            #pragma unroll
            for (int j = 31; j >= 0; j--) {
                u64 p2 = fma2(cr2, sr, mul2(ci2n, si));
                float pa, pb; up2(p2, pa, pb);
                pw[j*33 + lane] = pa + pb;
                u64 z2  = zw[j];
                u64 nsr = fma2(wr2, sr, fma2(wi2n, si, z2));
                si = fma2(wr2, si, mul2(wi2, sr));
                sr = nsr;
            }
            __syncwarp();
            float acc = 0.f;
            #pragma unroll
            for (int k = 0; k < 32; k++) acc += pw[lane*33 + k];
            yp[l0 + lane] = fmaf(d, zv, acc);
            __syncwarp();
        }
    }

    // ticket: second finisher applies gelu(yf+yb) -> g_yf (tf32-rounded for stage1 mma)
    __threadfence();
    int old = 0;
    if (lane == 0) old = atomicAdd(&g_cnt[bh], 1);
    old = __shfl_sync(0xffffffffu, old, 0);
    if (old == 1) {
        __threadfence();
        const float4* fa = (const float4*)(g_yf + (size_t)bh*LL);
        const float4* fb = (const float4*)(g_yb + (size_t)bh*LL);
        float4*       fo = (float4*)      (g_yf + (size_t)bh*LL);
        #pragma unroll
        for (int i = lane; i < LL/4; i += 32) {
            float4 a = fa[i], b = fb[i];
            float4 o;
            o.x = rtf(geluf(a.x + b.x));
            o.y = rtf(geluf(a.y + b.y));
            o.z = rtf(geluf(a.z + b.z));
            o.w = rtf(geluf(a.w + b.w));
            fo[i] = o;
        }
    }
}

// ================= tf32 tensor-core GEMM stages (cp.async double-buffered) =================
#define PW 36
#define PB 72
#define WS_SZ (128*PW)          // 4608 words
#define BS_SZ (32*PB)           // 2304 words
#define S1_WORDS (WS_SZ + BS_SZ)            // per buffer
#define S2_WORDS (2*WS_SZ + BS_SZ)
#define S1_BYTES (2*S1_WORDS*4)
#define S2_BYTES (2*S2_WORDS*4)

// issue async copy of one 128x32 weight chunk (pre-rounded tf32 floats)
__device__ __forceinline__ void cpw_issue(uint32_t wA, const float* __restrict__ W,
                                          int g0, int k0, int sk, int tid)
{
    int g = tid >> 1, h0 = (tid & 1) * 16;
    const float* src = W + (size_t)(g0 + g)*sk + k0 + h0;
    uint32_t dst = wA + (uint32_t)(g*PW + h0)*4u;
    #pragma unroll
    for (int i = 0; i < 4; i++) cpa16(dst + 16u*i, src + 4*i);
}
// issue async copy of one 32x64 activation chunk
__device__ __forceinline__ void cpb_issue(uint32_t bA, const float* __restrict__ Act,
                                          int k0, int l0, int tid)
{
    int hh = tid >> 3, lo = (tid & 7) * 8;
    const float* src = Act + (size_t)(k0 + hh)*LL + l0 + lo;
    uint32_t dst = bA + (uint32_t)(hh*PB + lo)*4u;
    cpa16(dst, src);
    cpa16(dst + 16u, src + 4);
}

__device__ __forceinline__ void mma_chunk(float d[2][4][4], const uint32_t* Ws, const uint32_t* Bsm,
                                          int wg, int wl, int gr, int tc)
{
    #pragma unroll
    for (int ks = 0; ks < 4; ks++) {
        int kk = ks*8;
        uint32_t a[2][4], bb[4][2];
        #pragma unroll
        for (int mi = 0; mi < 2; mi++) {
            const uint32_t* p = Ws + (wg + mi*16 + gr)*PW + kk + tc;
            a[mi][0] = p[0];
            a[mi][1] = p[8*PW];
            a[mi][2] = p[4];
            a[mi][3] = p[8*PW + 4];
        }
        #pragma unroll
        for (int ni = 0; ni < 4; ni++) {
            const uint32_t* p = Bsm + (kk + tc)*PB + wl + ni*8 + gr;
            bb[ni][0] = p[0];
            bb[ni][1] = p[4*PB];
        }
        #pragma unroll
        for (int mi = 0; mi < 2; mi++)
            #pragma unroll
            for (int ni = 0; ni < 4; ni++)
                mma8(d[mi][ni], a[mi], bb[ni]);
    }
}

// ---------------- stage1 ----------------
__global__ __launch_bounds__(256) void k_stage1(const float* __restrict__ bout,
                         const float* __restrict__ x, const float* __restrict__ bf)
{
    extern __shared__ uint32_t dsm[];
    const int b  = blockIdx.z;
    const int g0 = blockIdx.y * 128;
    const int l0 = blockIdx.x * 64;
    const int tid = threadIdx.x;
    const int w = tid >> 5, lane = tid & 31;
    const int wg = (w >> 1) * 32, wl = (w & 1) * 32;
    const int gr = lane >> 2, tc = lane & 3;

    uint32_t sb = (uint32_t)__cvta_generic_to_shared(dsm);
    uint32_t wA[2] = { sb, sb + (uint32_t)S1_WORDS*4u };
    uint32_t bA[2] = { sb + (uint32_t)WS_SZ*4u, sb + (uint32_t)(S1_WORDS + WS_SZ)*4u };

    float d[2][4][4];
    #pragma unroll
    for (int mi = 0; mi < 2; mi++)
        #pragma unroll
        for (int ni = 0; ni < 4; ni++)
            #pragma unroll
            for (int q = 0; q < 4; q++) d[mi][ni][q] = 0.f;

    const float* act = g_yf + (size_t)b*HH*LL;
    const float* ft  = g_ft + (size_t)b*FF*LL;

    cpw_issue(wA[0], g_WoutT, g0, 0, HH, tid);
    cpb_issue(bA[0], act, 0, l0, tid);
    cp_commit();

    for (int c = 0; c < 9; c++) {
        int cb = c & 1;
        if (c + 1 < 9) {
            int nb = cb ^ 1;
            if (c + 1 < 8) {
                cpw_issue(wA[nb], g_WoutT, g0, (c+1)*32, HH, tid);
                cpb_issue(bA[nb], act, (c+1)*32, l0, tid);
            } else {
                cpw_issue(wA[nb], g_WfT, g0, 0, FF, tid);
                cpb_issue(bA[nb], ft, 0, l0, tid);
            }
            cp_commit();
            cp_wait1();
        } else {
            cp_wait0();
        }
        __syncthreads();
        mma_chunk(d, dsm + cb*S1_WORDS, dsm + cb*S1_WORDS + WS_SZ, wg, wl, gr, tc);
        __syncthreads();
    }

    // epilogue: + bout + bf + tb + x, gate -> g_z (tf32-rounded for stage2 mma)
    #pragma unroll
    for (int mi = 0; mi < 2; mi++) {
        int ga = g0 + wg + mi*16 + gr;
        int gb2 = ga + 8;
        float basea = bout[ga]  + bf[ga]  + g_tb[b*HH + ga];
        float baseb = bout[gb2] + bf[gb2] + g_tb[b*HH + gb2];
        #pragma unroll
        for (int ni = 0; ni < 4; ni++) {
            int l = l0 + wl + ni*8 + 2*tc;
            size_t offa = ((size_t)b*HH + ga)*LL + l;
            size_t offb = ((size_t)b*HH + gb2)*LL + l;
            float2 xa = *(const float2*)(x + offa);
            float2 xb = *(const float2*)(x + offb);
            float2 ra, rb;
            ra.x = rtf(gatef(d[mi][ni][0] + basea + xa.x));
            ra.y = rtf(gatef(d[mi][ni][1] + basea + xa.y));
            rb.x = rtf(gatef(d[mi][ni][2] + baseb + xb.x));
            rb.y = rtf(gatef(d[mi][ni][3] + baseb + xb.y));
            *(float2*)(g_z + offa) = ra;
            *(float2*)(g_z + offb) = rb;
        }
    }
}

// ---------------- stage2 ----------------
__global__ __launch_bounds__(256) void k_stage2(const float* __restrict__ b1,
                         const float* __restrict__ b2,
                         const float* __restrict__ x, float* __restrict__ o1,
                         float* __restrict__ o2)
{
    extern __shared__ uint32_t dsm[];
    const int b  = blockIdx.z;
    const int g0 = blockIdx.y * 128;
    const int l0 = blockIdx.x * 64;
    const int tid = threadIdx.x;
    const int w = tid >> 5, lane = tid & 31;
    const int wg = (w >> 1) * 32, wl = (w & 1) * 32;
    const int gr = lane >> 2, tc = lane & 3;

    uint32_t sb = (uint32_t)__cvta_generic_to_shared(dsm);
    uint32_t w1A[2] = { sb, sb + (uint32_t)S2_WORDS*4u };
    uint32_t w2A[2] = { sb + (uint32_t)WS_SZ*4u, sb + (uint32_t)(S2_WORDS + WS_SZ)*4u };
    uint32_t bA[2]  = { sb + (uint32_t)(2*WS_SZ)*4u, sb + (uint32_t)(S2_WORDS + 2*WS_SZ)*4u };

    float d1[2][4][4], d2[2][4][4];
    #pragma unroll
    for (int mi = 0; mi < 2; mi++)
        #pragma unroll
        for (int ni = 0; ni < 4; ni++)
            #pragma unroll
            for (int q = 0; q < 4; q++) { d1[mi][ni][q] = 0.f; d2[mi][ni][q] = 0.f; }

    const float* gb = g_z + (size_t)b*HH*LL;

    cpw_issue(w1A[0], g_W1T, g0, 0, HH, tid);
    cpw_issue(w2A[0], g_W2T, g0, 0, HH, tid);
    cpb_issue(bA[0], gb, 0, l0, tid);
    cp_commit();

    for (int c = 0; c < 8; c++) {
        int cb = c & 1;
        if (c + 1 < 8) {
            int nb = cb ^ 1;
            cpw_issue(w1A[nb], g_W1T, g0, (c+1)*32, HH, tid);
            cpw_issue(w2A[nb], g_W2T, g0, (c+1)*32, HH, tid);
            cpb_issue(bA[nb], gb, (c+1)*32, l0, tid);
            cp_commit();
            cp_wait1();
        } else {
            cp_wait0();
        }
        __syncthreads();
        const uint32_t* W1s = dsm + cb*S2_WORDS;
        const uint32_t* W2s = W1s + WS_SZ;
        const uint32_t* Bsm = W1s + 2*WS_SZ;
        #pragma unroll
        for (int ks = 0; ks < 4; ks++) {
            int kk = ks*8;
            uint32_t a1[2][4], a2[2][4], bb[4][2];
            #pragma unroll
            for (int mi = 0; mi < 2; mi++) {
                const uint32_t* p1 = W1s + (wg + mi*16 + gr)*PW + kk + tc;
                a1[mi][0] = p1[0]; a1[mi][1] = p1[8*PW]; a1[mi][2] = p1[4]; a1[mi][3] = p1[8*PW + 4];
                const uint32_t* p2 = W2s + (wg + mi*16 + gr)*PW + kk + tc;
                a2[mi][0] = p2[0]; a2[mi][1] = p2[8*PW]; a2[mi][2] = p2[4]; a2[mi][3] = p2[8*PW + 4];
            }
            #pragma unroll
            for (int ni = 0; ni < 4; ni++) {
                const uint32_t* p = Bsm + (kk + tc)*PB + wl + ni*8 + gr;
                bb[ni][0] = p[0];
                bb[ni][1] = p[4*PB];
            }
            #pragma unroll
            for (int mi = 0; mi < 2; mi++)
                #pragma unroll
                for (int ni = 0; ni < 4; ni++) {
                    mma8(d1[mi][ni], a1[mi], bb[ni]);
                    mma8(d2[mi][ni], a2[mi], bb[ni]);
                }
        }
        __syncthreads();
    }

    // epilogue
    #pragma unroll
    for (int mi = 0; mi < 2; mi++) {
        int ga = g0 + wg + mi*16 + gr;
        int gb2 = ga + 8;
        float b1a = b1[ga], b1b = b1[gb2];
        float b2a = b2[ga], b2b = b2[gb2];
        #pragma unroll
        for (int ni = 0; ni < 4; ni++) {
            int l = l0 + wl + ni*8 + 2*tc;
            size_t offa = ((size_t)b*HH + ga)*LL + l;
            size_t offb = ((size_t)b*HH + gb2)*LL + l;
            float2 xa = *(const float2*)(x + offa);
            float2 xb = *(const float2*)(x + offb);
            float2 r;
            r.x = d1[mi][ni][0] + b1a + xa.x;
            r.y = d1[mi][ni][1] + b1a + xa.y;
            *(float2*)(o1 + offa) = r;
            r.x = d1[mi][ni][2] + b1b + xb.x;
            r.y = d1[mi][ni][3] + b1b + xb.y;
            *(float2*)(o1 + offb) = r;
            r.x = d2[mi][ni][0] + b2a;
            r.y = d2[mi][ni][1] + b2a;
            *(float2*)(o2 + offa) = r;
            r.x = d2[mi][ni][2] + b2b;
            r.y = d2[mi][ni][3] + b2b;
            *(float2*)(o2 + offb) = r;
        }
    }
}

// ---------------- launch ----------------
extern "C" void kernel_launch(void* const* d_in, const int* in_sizes, int n_in,
                              void* d_out, int out_size)
{
    const float* x        = (const float*)d_in[0];
    const float* t        = (const float*)d_in[1];
    const float* feat     = (const float*)d_in[2];
    const float* Wt       = (const float*)d_in[3];
    const float* bt       = (const float*)d_in[4];
    const float* ln_g     = (const float*)d_in[5];
    const float* ln_b     = (const float*)d_in[6];
    const float* log_dt   = (const float*)d_in[7];
    const float* logA_real= (const float*)d_in[8];
    const float* A_imag   = (const float*)d_in[9];
    const float* C_re     = (const float*)d_in[10];
    const float* C_im     = (const float*)d_in[11];
    const float* Dv       = (const float*)d_in[12];
    const float* Wout     = (const float*)d_in[13];
    const float* bout     = (const float*)d_in[14];
    const float* W1       = (const float*)d_in[15];
    const float* b1       = (const float*)d_in[16];
    const float* W2       = (const float*)d_in[17];
    const float* b2       = (const float*)d_in[18];
    const float* Wf       = (const float*)d_in[19];
    const float* bf       = (const float*)d_in[20];

    float* o1 = (float*)d_out;
    float* o2 = (float*)d_out + (size_t)BHL;

    cudaFuncSetAttribute(k_stage1, cudaFuncAttributeMaxDynamicSharedMemorySize, S1_BYTES);
    cudaFuncSetAttribute(k_stage2, cudaFuncAttributeMaxDynamicSharedMemorySize, S2_BYTES);

    k_zero<<<(BB*HH)/256, 256>>>();
    k_cvtw<<<(HH*HH)/256, 256>>>(Wout, W1, W2, Wf);
    k_cvtf<<<(BB*FF*LL)/256, 256>>>(feat);
    k_tb<<<BB, 256>>>(t, Wt, bt);
    k_ssm<<<(HH*NS+255)/256, 256>>>(log_dt, logA_real, A_imag, C_re, C_im);
    k_ln<<<dim3(LL/64, BB), 256>>>(x, ln_g, ln_b);
    k_scan<<<(2*BB*HH)/SCAN_WPB, 32*SCAN_WPB>>>(Dv);
    k_stage1<<<dim3(LL/64, HH/128, BB), 256, S1_BYTES>>>(bout, x, bf);
    k_stage2<<<dim3(LL/64, HH/128, BB), 256, S2_BYTES>>>(b1, b2, x, o1, o2);
}

// round 12
// speedup vs baseline: 1.4358x; 1.0306x over previous
#include <cuda_runtime.h>
#include <math.h>
#include <stdint.h>

#define BB 32
#define HH 256
#define LL 2048
#define NS 64
#define FF 32
#define BHL (BB*HH*LL)

typedef unsigned long long u64;

// ---------------- f32x2 helpers ----------------
__device__ __forceinline__ u64 pk2(float lo, float hi) {
    u64 r; asm("mov.b64 %0, {%1, %2};" : "=l"(r) : "f"(lo), "f"(hi)); return r;
}
__device__ __forceinline__ void up2(u64 v, float& a, float& b) {
    asm("mov.b64 {%0, %1}, %2;" : "=f"(a), "=f"(b) : "l"(v));
}
__device__ __forceinline__ u64 fma2(u64 a, u64 b, u64 c) {
    u64 d; asm("fma.rn.f32x2 %0, %1, %2, %3;" : "=l"(d) : "l"(a), "l"(b), "l"(c)); return d;
}
__device__ __forceinline__ u64 mul2(u64 a, u64 b) {
    u64 d; asm("mul.rn.f32x2 %0, %1, %2;" : "=l"(d) : "l"(a), "l"(b)); return d;
}

// ---------------- tf32 helpers ----------------
__device__ __forceinline__ uint32_t tf32c(float x) {
    uint32_t r; asm("cvt.rna.tf32.f32 %0, %1;" : "=r"(r) : "f"(x)); return r;
}
__device__ __forceinline__ float rtf(float x) { return __uint_as_float(tf32c(x)); }
__device__ __forceinline__ void mma8(float d[4], const uint32_t a[4], const uint32_t b[2]) {
    asm("mma.sync.aligned.m16n8k8.row.col.f32.tf32.tf32.f32 "
        "{%0,%1,%2,%3}, {%4,%5,%6,%7}, {%8,%9}, {%0,%1,%2,%3};"
        : "+f"(d[0]), "+f"(d[1]), "+f"(d[2]), "+f"(d[3])
        : "r"(a[0]), "r"(a[1]), "r"(a[2]), "r"(a[3]), "r"(b[0]), "r"(b[1]));
}

// ---------------- cp.async helpers ----------------
__device__ __forceinline__ void cpa16(uint32_t s, const float* g) {
    asm volatile("cp.async.cg.shared.global [%0], [%1], 16;" :: "r"(s), "l"(g));
}
__device__ __forceinline__ void cp_commit() { asm volatile("cp.async.commit_group;"); }
__device__ __forceinline__ void cp_wait1()  { asm volatile("cp.async.wait_group 1;"); }
__device__ __forceinline__ void cp_wait0()  { asm volatile("cp.async.wait_group 0;"); }

__device__ __forceinline__ float gatef(float o) {
    float u = __expf(fminf(-o, 25.f));
    float u2 = u * u;
    return (1.f - u2) / ((1.f + u2) * (1.f + u));
}
__device__ __forceinline__ float geluf(float y) {
    float u = 0.7978845608028654f * fmaf(0.044715f*y, y*y, y);
    float e = __expf(fminf(-2.f*u, 80.f));
    float th = (1.f - e) / (1.f + e);
    return 0.5f*y*(1.f + th);
}

// ---------------- scratch ----------------
__device__ float g_tb[BB*HH];
__device__ float g_wr[HH*NS], g_wi[HH*NS];
__device__ float g_c0r[HH*NS], g_c0i[HH*NS], g_c1r[HH*NS], g_c1i[HH*NS];
__device__ float g_z [BHL];
__device__ float g_yf[BHL];   // fwd scan out; after ticket: tf32(gelu(yf+yb+D*z))
__device__ float g_yb[BHL];
__device__ int   g_cnt[BB*HH];
// tf32-pre-rounded GEMM operands
__device__ float g_WoutT[HH*HH], g_W1T[HH*HH], g_W2T[HH*HH], g_WfT[HH*FF];
__device__ float g_ft[BB*FF*LL];

// ---------------- pre-round weights to tf32 ----------------
__global__ void k_cvtw(const float* __restrict__ Wout, const float* __restrict__ W1,
                       const float* __restrict__ W2, const float* __restrict__ Wf)
{
    int i = blockIdx.x*256 + threadIdx.x;      // 0..65535
    g_WoutT[i] = rtf(Wout[i]);
    g_W1T[i]   = rtf(W1[i]);
    g_W2T[i]   = rtf(W2[i]);
    if (i < HH*FF) g_WfT[i] = rtf(Wf[i]);
}

// ---------------- t @ Wt^T + bt (128 blocks; 4 threads per output, k-split) ----------------
__global__ void k_tb(const float* __restrict__ t, const float* __restrict__ Wt,
                     const float* __restrict__ bt)
{
    __shared__ float ts[HH];
    __shared__ float part[64][4];
    int b  = blockIdx.y;
    int h0 = blockIdx.x * 64;
    int tid = threadIdx.x;
    ts[tid] = t[b*HH + tid];
    __syncthreads();
    int hl = tid >> 2, ks = tid & 3;
    int h = h0 + hl;
    const float* wrow = Wt + (size_t)h*HH + ks*64;
    const float* tsp  = ts + ks*64;
    float acc = 0.f;
    #pragma unroll 16
    for (int k = 0; k < 64; k++) acc = fmaf(tsp[k], wrow[k], acc);
    part[hl][ks] = acc;
    __syncthreads();
    if (ks == 0)
        g_tb[b*HH + h] = part[hl][0] + part[hl][1] + part[hl][2] + part[hl][3] + bt[h];
}

// ---------------- SSM parameter prep (+ ticket zeroing folded in) ----------------
__global__ void k_ssm(const float* __restrict__ log_dt, const float* __restrict__ logA_real,
                      const float* __restrict__ A_imag, const float* __restrict__ C_re,
                      const float* __restrict__ C_im)
{
    int i = blockIdx.x*blockDim.x + threadIdx.x;
    if (i >= HH*NS) return;
    if (i < BB*HH) g_cnt[i] = 0;               // fold k_zero here
    int h = i / NS;
    float dt = expf(log_dt[h]);
    float Ar = -expf(logA_real[i]);
    float Ai = A_imag[i];
    float dr = dt*Ar, di = dt*Ai;
    float er = expf(dr);
    float wr = er*cosf(di), wi = er*sinf(di);
    g_wr[i] = wr; g_wi[i] = wi;
    float Er = wr - 1.0f, Ei = wi;
    float inv = 1.0f/(Ar*Ar + Ai*Ai);
    float qr = (Er*Ar + Ei*Ai)*inv;
    float qi = (Ei*Ar - Er*Ai)*inv;
    {
        float cr = C_re[i], ci = C_im[i];
        g_c0r[i] = 2.0f*(cr*qr - ci*qi);
        g_c0i[i] = 2.0f*(cr*qi + ci*qr);
    }
    {
        float cr = C_re[HH*NS + i], ci = C_im[HH*NS + i];
        g_c1r[i] = 2.0f*(cr*qr - ci*qi);
        g_c1i[i] = 2.0f*(cr*qi + ci*qr);
    }
}

// ---------------- LayerNorm over H -> z (4-way h-split) + feat tf32 conversion tail ----------------
__global__ void k_ln(const float* __restrict__ x, const float* __restrict__ ln_g,
                     const float* __restrict__ ln_b, const float* __restrict__ feat)
{
    __shared__ float tbs[HH], gs[HH], bs[HH];
    __shared__ float sms[4][64], smss[4][64];
    int b = blockIdx.y;
    int tid = threadIdx.x;
    tbs[tid] = g_tb[b*HH + tid];
    gs[tid]  = ln_g[tid];
    bs[tid]  = ln_b[tid];
    __syncthreads();
    int lg = tid & 63, hg = tid >> 6;
    int l = blockIdx.x*64 + lg;
    const float* xb = x + (size_t)b*HH*LL + l;
    float s = 0.f, ss = 0.f;
    #pragma unroll 8
    for (int h = hg*64; h < hg*64 + 64; h++) {
        float v = xb[(size_t)h*LL] + tbs[h];
        s += v; ss = fmaf(v, v, ss);
    }
    sms[hg][lg] = s; smss[hg][lg] = ss;
    __syncthreads();
    float st  = sms[0][lg]  + sms[1][lg]  + sms[2][lg]  + sms[3][lg];
    float sst = smss[0][lg] + smss[1][lg] + smss[2][lg] + smss[3][lg];
    float mu  = st * (1.0f/HH);
    float var = sst*(1.0f/HH) - mu*mu;
    float rstd = rsqrtf(var + 1e-5f);
    float* zb = g_z + (size_t)b*HH*LL + l;
    #pragma unroll 8
    for (int h = hg*64; h < hg*64 + 64; h++) {
        float v = xb[(size_t)h*LL] + tbs[h];
        zb[(size_t)h*LL] = (v - mu)*rstd*gs[h] + bs[h];
    }
    // tail: feat -> tf32 pre-round (independent; saves the k_cvtf launch)
    {
        int gidx = (b*32 + blockIdx.x)*256 + tid;   // 0..262143, x-grid is exactly 32
        const float4* fs = (const float4*)feat;
        float4* fd = (float4*)g_ft;
        #pragma unroll
        for (int q = 0; q < 2; q++) {
            float4 v = fs[gidx*2 + q];
            v.x = rtf(v.x); v.y = rtf(v.y); v.z = rtf(v.z); v.w = rtf(v.w);
            fd[gidx*2 + q] = v;
        }
    }
}

// ---------------- scan (R8 best config) + fused gelu ticket (tf32-rounded store) ----------------
#define SCAN_WPB 4
__global__ __launch_bounds__(32*SCAN_WPB) void k_scan(const float* __restrict__ Dv)
{
    __shared__ __align__(16) float pbuf[SCAN_WPB][32*33];
    __shared__ __align__(16) u64   zbuf[SCAN_WPB][32];
    int wid  = threadIdx.x >> 5;
    int lane = threadIdx.x & 31;
    int gw   = blockIdx.x*SCAN_WPB + wid;
    int bh   = gw >> 1;
    int dir  = gw & 1;
    int h    = bh & (HH-1);
    int ci   = h*NS + lane;
    float* pw = pbuf[wid];
    u64*   zw = zbuf[wid];

    u64 wr2  = pk2(g_wr[ci],  g_wr[ci+32]);
    u64 wi2  = pk2(g_wi[ci],  g_wi[ci+32]);
    u64 wi2n = pk2(-g_wi[ci], -g_wi[ci+32]);
    u64 cr2, ci2n;
    if (dir == 0) { cr2 = pk2(g_c0r[ci], g_c0r[ci+32]); ci2n = pk2(-g_c0i[ci], -g_c0i[ci+32]); }
    else          { cr2 = pk2(g_c1r[ci], g_c1r[ci+32]); ci2n = pk2(-g_c1i[ci], -g_c1i[ci+32]); }

    const float* zp = g_z + (size_t)bh*LL;
    float* yp = (dir == 0 ? g_yf : g_yb) + (size_t)bh*LL;

    u64 sr = 0ULL, si = 0ULL;

    if (dir == 0) {
        for (int t = 0; t < LL/32; t++) {
            int l0 = t*32;
            float zv = zp[l0 + lane];
            zw[lane] = pk2(zv, zv);
            __syncwarp();
            #pragma unroll
            for (int j = 0; j < 32; j++) {
                u64 z2  = zw[j];
                u64 nsr = fma2(wr2, sr, fma2(wi2n, si, z2));
                si = fma2(wr2, si, mul2(wi2, sr));
                sr = nsr;
                u64 p2 = fma2(cr2, sr, mul2(ci2n, si));
                float pa, pb; up2(p2, pa, pb);
                pw[j*33 + lane] = pa + pb;
            }
            __syncwarp();
            float acc = 0.f;
            #pragma unroll
            for (int k = 0; k < 32; k++) acc += pw[lane*33 + k];
            yp[l0 + lane] = acc;
            __syncwarp();
        }
    } else {
        float d = Dv[h];
        for (int t = 0; t < LL/32; t++) {
            int l0 = LL - 32*(t+1);
            float zv = zp[l0 + lane];
            zw[lane] = pk2(zv, zv);
            __syncwarp();
            #pragma unroll
            for (int j = 31; j >= 0; j--) {
                u64 p2 = fma2(cr2, sr, mul2(ci2n, si));
                float pa, pb; up2(p2, pa, pb);
                pw[j*33 + lane] = pa + pb;
                u64 z2  = zw[j];
                u64 nsr = fma2(wr2, sr, fma2(wi2n, si, z2));
                si = fma2(wr2, si, mul2(wi2, sr));
                sr = nsr;
            }
            __syncwarp();
            float acc = 0.f;
            #pragma unroll
            for (int k = 0; k < 32; k++) acc += pw[lane*33 + k];
            yp[l0 + lane] = fmaf(d, zv, acc);
            __syncwarp();
        }
    }

    // ticket: second finisher applies gelu(yf+yb) -> g_yf (tf32-rounded for stage1 mma)
    __threadfence();
    int old = 0;
    if (lane == 0) old = atomicAdd(&g_cnt[bh], 1);
    old = __shfl_sync(0xffffffffu, old, 0);
    if (old == 1) {
        __threadfence();
        const float4* fa = (const float4*)(g_yf + (size_t)bh*LL);
        const float4* fb = (const float4*)(g_yb + (size_t)bh*LL);
        float4*       fo = (float4*)      (g_yf + (size_t)bh*LL);
        #pragma unroll
        for (int i = lane; i < LL/4; i += 32) {
            float4 a = fa[i], b = fb[i];
            float4 o;
            o.x = rtf(geluf(a.x + b.x));
            o.y = rtf(geluf(a.y + b.y));
            o.z = rtf(geluf(a.z + b.z));
            o.w = rtf(geluf(a.w + b.w));
            fo[i] = o;
        }
    }
}

// ================= tf32 tensor-core GEMM stages (cp.async double-buffered) =================
#define PW 36
#define PB 72
#define WS_SZ (128*PW)
#define BS_SZ (32*PB)
#define S1_WORDS (WS_SZ + BS_SZ)
#define S2_WORDS (2*WS_SZ + BS_SZ)
#define S1_BYTES (2*S1_WORDS*4)
#define S2_BYTES (2*S2_WORDS*4)

__device__ __forceinline__ void cpw_issue(uint32_t wA, const float* __restrict__ W,
                                          int g0, int k0, int sk, int tid)
{
    int g = tid >> 1, h0 = (tid & 1) * 16;
    const float* src = W + (size_t)(g0 + g)*sk + k0 + h0;
    uint32_t dst = wA + (uint32_t)(g*PW + h0)*4u;
    #pragma unroll
    for (int i = 0; i < 4; i++) cpa16(dst + 16u*i, src + 4*i);
}
__device__ __forceinline__ void cpb_issue(uint32_t bA, const float* __restrict__ Act,
                                          int k0, int l0, int tid)
{
    int hh = tid >> 3, lo = (tid & 7) * 8;
    const float* src = Act + (size_t)(k0 + hh)*LL + l0 + lo;
    uint32_t dst = bA + (uint32_t)(hh*PB + lo)*4u;
    cpa16(dst, src);
    cpa16(dst + 16u, src + 4);
}

__device__ __forceinline__ void mma_chunk(float d[2][4][4], const uint32_t* Ws, const uint32_t* Bsm,
                                          int wg, int wl, int gr, int tc)
{
    #pragma unroll
    for (int ks = 0; ks < 4; ks++) {
        int kk = ks*8;
        uint32_t a[2][4], bb[4][2];
        #pragma unroll
        for (int mi = 0; mi < 2; mi++) {
            const uint32_t* p = Ws + (wg + mi*16 + gr)*PW + kk + tc;
            a[mi][0] = p[0];
            a[mi][1] = p[8*PW];
            a[mi][2] = p[4];
            a[mi][3] = p[8*PW + 4];
        }
        #pragma unroll
        for (int ni = 0; ni < 4; ni++) {
            const uint32_t* p = Bsm + (kk + tc)*PB + wl + ni*8 + gr;
            bb[ni][0] = p[0];
            bb[ni][1] = p[4*PB];
        }
        #pragma unroll
        for (int mi = 0; mi < 2; mi++)
            #pragma unroll
            for (int ni = 0; ni < 4; ni++)
                mma8(d[mi][ni], a[mi], bb[ni]);
    }
}

// ---------------- stage1 ----------------
__global__ __launch_bounds__(256) void k_stage1(const float* __restrict__ bout,
                         const float* __restrict__ x, const float* __restrict__ bf)
{
    extern __shared__ uint32_t dsm[];
    const int b  = blockIdx.z;
    const int g0 = blockIdx.y * 128;
    const int l0 = blockIdx.x * 64;
    const int tid = threadIdx.x;
    const int w = tid >> 5, lane = tid & 31;
    const int wg = (w >> 1) * 32, wl = (w & 1) * 32;
    const int gr = lane >> 2, tc = lane & 3;

    uint32_t sb = (uint32_t)__cvta_generic_to_shared(dsm);
    uint32_t wA[2] = { sb, sb + (uint32_t)S1_WORDS*4u };
    uint32_t bA[2] = { sb + (uint32_t)WS_SZ*4u, sb + (uint32_t)(S1_WORDS + WS_SZ)*4u };

    float d[2][4][4];
    #pragma unroll
    for (int mi = 0; mi < 2; mi++)
        #pragma unroll
        for (int ni = 0; ni < 4; ni++)
            #pragma unroll
            for (int q = 0; q < 4; q++) d[mi][ni][q] = 0.f;

    const float* act = g_yf + (size_t)b*HH*LL;
    const float* ft  = g_ft + (size_t)b*FF*LL;

    cpw_issue(wA[0], g_WoutT, g0, 0, HH, tid);
    cpb_issue(bA[0], act, 0, l0, tid);
    cp_commit();

    for (int c = 0; c < 9; c++) {
        int cb = c & 1;
        if (c + 1 < 9) {
            int nb = cb ^ 1;
            if (c + 1 < 8) {
                cpw_issue(wA[nb], g_WoutT, g0, (c+1)*32, HH, tid);
                cpb_issue(bA[nb], act, (c+1)*32, l0, tid);
            } else {
                cpw_issue(wA[nb], g_WfT, g0, 0, FF, tid);
                cpb_issue(bA[nb], ft, 0, l0, tid);
            }
            cp_commit();
            cp_wait1();
        } else {
            cp_wait0();
        }
        __syncthreads();
        mma_chunk(d, dsm + cb*S1_WORDS, dsm + cb*S1_WORDS + WS_SZ, wg, wl, gr, tc);
        __syncthreads();
    }

    #pragma unroll
    for (int mi = 0; mi < 2; mi++) {
        int ga = g0 + wg + mi*16 + gr;
        int gb2 = ga + 8;
        float basea = bout[ga]  + bf[ga]  + g_tb[b*HH + ga];
        float baseb = bout[gb2] + bf[gb2] + g_tb[b*HH + gb2];
        #pragma unroll
        for (int ni = 0; ni < 4; ni++) {
            int l = l0 + wl + ni*8 + 2*tc;
            size_t offa = ((size_t)b*HH + ga)*LL + l;
            size_t offb = ((size_t)b*HH + gb2)*LL + l;
            float2 xa = *(const float2*)(x + offa);
            float2 xb = *(const float2*)(x + offb);
            float2 ra, rb;
            ra.x = rtf(gatef(d[mi][ni][0] + basea + xa.x));
            ra.y = rtf(gatef(d[mi][ni][1] + basea + xa.y));
            rb.x = rtf(gatef(d[mi][ni][2] + baseb + xb.x));
            rb.y = rtf(gatef(d[mi][ni][3] + baseb + xb.y));
            *(float2*)(g_z + offa) = ra;
            *(float2*)(g_z + offb) = rb;
        }
    }
}

// ---------------- stage2 ----------------
__global__ __launch_bounds__(256) void k_stage2(const float* __restrict__ b1,
                         const float* __restrict__ b2,
                         const float* __restrict__ x, float* __restrict__ o1,
                         float* __restrict__ o2)
{
    extern __shared__ uint32_t dsm[];
    const int b  = blockIdx.z;
    const int g0 = blockIdx.y * 128;
    const int l0 = blockIdx.x * 64;
    const int tid = threadIdx.x;
    const int w = tid >> 5, lane = tid & 31;
    const int wg = (w >> 1) * 32, wl = (w & 1) * 32;
    const int gr = lane >> 2, tc = lane & 3;

    uint32_t sb = (uint32_t)__cvta_generic_to_shared(dsm);
    uint32_t w1A[2] = { sb, sb + (uint32_t)S2_WORDS*4u };
    uint32_t w2A[2] = { sb + (uint32_t)WS_SZ*4u, sb + (uint32_t)(S2_WORDS + WS_SZ)*4u };
    uint32_t bA[2]  = { sb + (uint32_t)(2*WS_SZ)*4u, sb + (uint32_t)(S2_WORDS + 2*WS_SZ)*4u };

    float d1[2][4][4], d2[2][4][4];
    #pragma unroll
    for (int mi = 0; mi < 2; mi++)
        #pragma unroll
        for (int ni = 0; ni < 4; ni++)
            #pragma unroll
            for (int q = 0; q < 4; q++) { d1[mi][ni][q] = 0.f; d2[mi][ni][q] = 0.f; }

    const float* gb = g_z + (size_t)b*HH*LL;

    cpw_issue(w1A[0], g_W1T, g0, 0, HH, tid);
    cpw_issue(w2A[0], g_W2T, g0, 0, HH, tid);
    cpb_issue(bA[0], gb, 0, l0, tid);
    cp_commit();

    for (int c = 0; c < 8; c++) {
        int cb = c & 1;
        if (c + 1 < 8) {
            int nb = cb ^ 1;
            cpw_issue(w1A[nb], g_W1T, g0, (c+1)*32, HH, tid);
            cpw_issue(w2A[nb], g_W2T, g0, (c+1)*32, HH, tid);
            cpb_issue(bA[nb], gb, (c+1)*32, l0, tid);
            cp_commit();
            cp_wait1();
        } else {
            cp_wait0();
        }
        __syncthreads();
        const uint32_t* W1s = dsm + cb*S2_WORDS;
        const uint32_t* W2s = W1s + WS_SZ;
        const uint32_t* Bsm = W1s + 2*WS_SZ;
        #pragma unroll
        for (int ks = 0; ks < 4; ks++) {
            int kk = ks*8;
            uint32_t a1[2][4], a2[2][4], bb[4][2];
            #pragma unroll
            for (int mi = 0; mi < 2; mi++) {
                const uint32_t* p1 = W1s + (wg + mi*16 + gr)*PW + kk + tc;
                a1[mi][0] = p1[0]; a1[mi][1] = p1[8*PW]; a1[mi][2] = p1[4]; a1[mi][3] = p1[8*PW + 4];
                const uint32_t* p2 = W2s + (wg + mi*16 + gr)*PW + kk + tc;
                a2[mi][0] = p2[0]; a2[mi][1] = p2[8*PW]; a2[mi][2] = p2[4]; a2[mi][3] = p2[8*PW + 4];
            }
            #pragma unroll
            for (int ni = 0; ni < 4; ni++) {
                const uint32_t* p = Bsm + (kk + tc)*PB + wl + ni*8 + gr;
                bb[ni][0] = p[0];
                bb[ni][1] = p[4*PB];
            }
            #pragma unroll
            for (int mi = 0; mi < 2; mi++)
                #pragma unroll
                for (int ni = 0; ni < 4; ni++) {
                    mma8(d1[mi][ni], a1[mi], bb[ni]);
                    mma8(d2[mi][ni], a2[mi], bb[ni]);
                }
        }
        __syncthreads();
    }

    #pragma unroll
    for (int mi = 0; mi < 2; mi++) {
        int ga = g0 + wg + mi*16 + gr;
        int gb2 = ga + 8;
        float b1a = b1[ga], b1b = b1[gb2];
        float b2a = b2[ga], b2b = b2[gb2];
        #pragma unroll
        for (int ni = 0; ni < 4; ni++) {
            int l = l0 + wl + ni*8 + 2*tc;
            size_t offa = ((size_t)b*HH + ga)*LL + l;
            size_t offb = ((size_t)b*HH + gb2)*LL + l;
            float2 xa = *(const float2*)(x + offa);
            float2 xb = *(const float2*)(x + offb);
            float2 r;
            r.x = d1[mi][ni][0] + b1a + xa.x;
            r.y = d1[mi][ni][1] + b1a + xa.y;
            *(float2*)(o1 + offa) = r;
            r.x = d1[mi][ni][2] + b1b + xb.x;
            r.y = d1[mi][ni][3] + b1b + xb.y;
            *(float2*)(o1 + offb) = r;
            r.x = d2[mi][ni][0] + b2a;
            r.y = d2[mi][ni][1] + b2a;
            *(float2*)(o2 + offa) = r;
            r.x = d2[mi][ni][2] + b2b;
            r.y = d2[mi][ni][3] + b2b;
            *(float2*)(o2 + offb) = r;
        }
    }
}

// ---------------- launch ----------------
extern "C" void kernel_launch(void* const* d_in, const int* in_sizes, int n_in,
                              void* d_out, int out_size)
{
    const float* x        = (const float*)d_in[0];
    const float* t        = (const float*)d_in[1];
    const float* feat     = (const float*)d_in[2];
    const float* Wt       = (const float*)d_in[3];
    const float* bt       = (const float*)d_in[4];
    const float* ln_g     = (const float*)d_in[5];
    const float* ln_b     = (const float*)d_in[6];
    const float* log_dt   = (const float*)d_in[7];
    const float* logA_real= (const float*)d_in[8];
    const float* A_imag   = (const float*)d_in[9];
    const float* C_re     = (const float*)d_in[10];
    const float* C_im     = (const float*)d_in[11];
    const float* Dv       = (const float*)d_in[12];
    const float* Wout     = (const float*)d_in[13];
    const float* bout     = (const float*)d_in[14];
    const float* W1       = (const float*)d_in[15];
    const float* b1       = (const float*)d_in[16];
    const float* W2       = (const float*)d_in[17];
    const float* b2       = (const float*)d_in[18];
    const float* Wf       = (const float*)d_in[19];
    const float* bf       = (const float*)d_in[20];

    float* o1 = (float*)d_out;
    float* o2 = (float*)d_out + (size_t)BHL;

    cudaFuncSetAttribute(k_stage1, cudaFuncAttributeMaxDynamicSharedMemorySize, S1_BYTES);
    cudaFuncSetAttribute(k_stage2, cudaFuncAttributeMaxDynamicSharedMemorySize, S2_BYTES);

    k_cvtw<<<(HH*HH)/256, 256>>>(Wout, W1, W2, Wf);
    k_tb<<<dim3(4, BB), 256>>>(t, Wt, bt);
    k_ssm<<<(HH*NS+255)/256, 256>>>(log_dt, logA_real, A_imag, C_re, C_im);
    k_ln<<<dim3(LL/64, BB), 256>>>(x, ln_g, ln_b, feat);
    k_scan<<<(2*BB*HH)/SCAN_WPB, 32*SCAN_WPB>>>(Dv);
    k_stage1<<<dim3(LL/64, HH/128, BB), 256, S1_BYTES>>>(bout, x, bf);
    k_stage2<<<dim3(LL/64, HH/128, BB), 256, S2_BYTES>>>(b1, b2, x, o1, o2);
}

// round 14
// speedup vs baseline: 1.6480x; 1.1478x over previous
#include <cuda_runtime.h>
#include <math.h>
#include <stdint.h>

#define BB 32
#define HH 256
#define LL 2048
#define NS 64
#define FF 32
#define BHL (BB*HH*LL)
#define TT 64
#define NCH 32

// ---------------- tf32 helpers ----------------
__device__ __forceinline__ uint32_t tf32c(float x) {
    uint32_t r; asm("cvt.rna.tf32.f32 %0, %1;" : "=r"(r) : "f"(x)); return r;
}
__device__ __forceinline__ float rtf(float x) { return __uint_as_float(tf32c(x)); }
__device__ __forceinline__ void mma8(float d[4], const uint32_t a[4], const uint32_t b[2]) {
    asm("mma.sync.aligned.m16n8k8.row.col.f32.tf32.tf32.f32 "
        "{%0,%1,%2,%3}, {%4,%5,%6,%7}, {%8,%9}, {%0,%1,%2,%3};"
        : "+f"(d[0]), "+f"(d[1]), "+f"(d[2]), "+f"(d[3])
        : "r"(a[0]), "r"(a[1]), "r"(a[2]), "r"(a[3]), "r"(b[0]), "r"(b[1]));
}

// ---------------- cp.async helpers ----------------
__device__ __forceinline__ void cpa16(uint32_t s, const float* g) {
    asm volatile("cp.async.cg.shared.global [%0], [%1], 16;" :: "r"(s), "l"(g));
}
__device__ __forceinline__ void cp_commit() { asm volatile("cp.async.commit_group;"); }
__device__ __forceinline__ void cp_wait1()  { asm volatile("cp.async.wait_group 1;"); }
__device__ __forceinline__ void cp_wait0()  { asm volatile("cp.async.wait_group 0;"); }

__device__ __forceinline__ float gatef(float o) {
    float u = __expf(fminf(-o, 25.f));
    float u2 = u * u;
    return (1.f - u2) / ((1.f + u2) * (1.f + u));
}
__device__ __forceinline__ float geluf(float y) {
    float u = 0.7978845608028654f * fmaf(0.044715f*y, y*y, y);
    float e = __expf(fminf(-2.f*u, 80.f));
    float th = (1.f - e) / (1.f + e);
    return 0.5f*y*(1.f + th);
}

// ---------------- scratch ----------------
__device__ float g_tb[BB*HH];
__device__ float g_z [BHL];
__device__ float g_yf[BHL];   // fwd scan out; after ticket: tf32(gelu(yf+yb))
__device__ float g_yb[BHL];   // bwd scan out (+ D*z folded)
__device__ int   g_cnt[BB*HH];
// tf32-pre-rounded GEMM operands
__device__ float g_WoutT[HH*HH], g_W1T[HH*HH], g_W2T[HH*HH], g_WfT[HH*FF];
__device__ float g_ft[BB*FF*LL];
// chunked-scan matrices per (h,dir)
__device__ float g_G[2*HH][64*192];   // [Ktoeplitz | CO_re | -CO_im]
__device__ float g_H[2*HH][128*64];   // [WA_re ; WA_im]
__device__ float g_wTd[2*HH][128];    // w^64 re(0..63), im(64..127)

// ---------------- pre-round weights to tf32 (+ zero tickets) ----------------
__global__ void k_cvtw(const float* __restrict__ Wout, const float* __restrict__ W1,
                       const float* __restrict__ W2, const float* __restrict__ Wf)
{
    int i = blockIdx.x*256 + threadIdx.x;      // 0..65535
    g_WoutT[i] = rtf(Wout[i]);
    g_W1T[i]   = rtf(W1[i]);
    g_W2T[i]   = rtf(W2[i]);
    if (i < HH*FF) g_WfT[i] = rtf(Wf[i]);
    if (i < HH) g_cnt[i] = 0;
}

// ---------------- t @ Wt^T + bt ----------------
__global__ void k_tb(const float* __restrict__ t, const float* __restrict__ Wt,
                     const float* __restrict__ bt)
{
    __shared__ float ts[HH];
    __shared__ float part[64][4];
    int b  = blockIdx.y;
    int h0 = blockIdx.x * 64;
    int tid = threadIdx.x;
    ts[tid] = t[b*HH + tid];
    __syncthreads();
    int hl = tid >> 2, ks = tid & 3;
    int h = h0 + hl;
    const float* wrow = Wt + (size_t)h*HH + ks*64;
    const float* tsp  = ts + ks*64;
    float acc = 0.f;
    #pragma unroll 16
    for (int k = 0; k < 64; k++) acc = fmaf(tsp[k], wrow[k], acc);
    part[hl][ks] = acc;
    __syncthreads();
    if (ks == 0)
        g_tb[b*HH + h] = part[hl][0] + part[hl][1] + part[hl][2] + part[hl][3] + bt[h];
}

// ---------------- chunked-scan matrix prep: one block per (h,dir) ----------------
__global__ void k_prep(const float* __restrict__ log_dt, const float* __restrict__ logA_real,
                       const float* __restrict__ A_imag, const float* __restrict__ C_re,
                       const float* __restrict__ C_im)
{
    __shared__ float Ere[65][64], Eim[65][64];
    __shared__ float cdr[64], cdi[64], kv[64], sdr[64], sdi[64];
    int hd = blockIdx.x, h = hd >> 1, dir = hd & 1;
    int tid = threadIdx.x;
    if (tid < 64) {
        int n = tid, i = h*NS + n;
        float dt = expf(log_dt[h]);
        float Ar = -expf(logA_real[i]);
        float Ai = A_imag[i];
        float dr = dt*Ar, di = dt*Ai;
        sdr[n] = dr; sdi[n] = di;
        float er = expf(dr);
        float wr = er*cosf(di), wi = er*sinf(di);
        float Er = wr - 1.f, Ei = wi;
        float inv = 1.f/(Ar*Ar + Ai*Ai);
        float qr = (Er*Ar + Ei*Ai)*inv;
        float qi = (Ei*Ar - Er*Ai)*inv;
        float cr = C_re[dir*HH*NS + i], ci = C_im[dir*HH*NS + i];
        cdr[n] = 2.f*(cr*qr - ci*qi);
        cdi[n] = 2.f*(cr*qi + ci*qr);
    }
    __syncthreads();
    for (int q = tid; q < 65*64; q += 256) {
        int p = q >> 6, n = q & 63;
        float e  = expf((float)p*sdr[n]);
        float ph = (float)p*sdi[n];
        Ere[p][n] = e*cosf(ph);
        Eim[p][n] = e*sinf(ph);
    }
    __syncthreads();
    if (tid < 64) {
        int p = tid;
        float acc = 0.f;
        for (int n = 0; n < 64; n++) acc += cdr[n]*Ere[p][n] - cdi[n]*Eim[p][n];
        kv[p] = acc;
    }
    __syncthreads();
    float* Gp = g_G[hd];
    for (int q = tid; q < 64*192; q += 256) {
        int i = q / 192, col = q % 192;
        float val;
        if (col < 64) {
            int j = col;
            if (!dir) val = (j <= i) ? kv[i-j] : 0.f;
            else      val = (j >  i) ? kv[j-i-1] : 0.f;   // FIX: z[l+1] carries w^0
        } else {
            int n = (col - 64) & 63;
            int p = dir ? (63 - i) : (i + 1);
            float core = cdr[n]*Ere[p][n] - cdi[n]*Eim[p][n];
            float coim = cdr[n]*Eim[p][n] + cdi[n]*Ere[p][n];
            val = (col < 128) ? core : -coim;
        }
        Gp[q] = rtf(val);
    }
    float* Hp = g_H[hd];
    for (int q = tid; q < 128*64; q += 256) {
        int r = q >> 6, j = q & 63;
        int n = r & 63;
        int p = dir ? j : (63 - j);                        // FIX: S gathers w^j (not w^{j+1})
        float val = (r < 64) ? Ere[p][n] : Eim[p][n];
        Hp[q] = rtf(val);
    }
    if (tid < 64) {
        g_wTd[hd][tid]    = Ere[64][tid];
        g_wTd[hd][64+tid] = Eim[64][tid];
    }
}

// ---------------- LayerNorm over H -> z (tf32-rounded) + feat tf32 tail ----------------
__global__ void k_ln(const float* __restrict__ x, const float* __restrict__ ln_g,
                     const float* __restrict__ ln_b, const float* __restrict__ feat)
{
    __shared__ float tbs[HH], gs[HH], bs[HH];
    __shared__ float sms[4][64], smss[4][64];
    int b = blockIdx.y;
    int tid = threadIdx.x;
    tbs[tid] = g_tb[b*HH + tid];
    gs[tid]  = ln_g[tid];
    bs[tid]  = ln_b[tid];
    __syncthreads();
    int lg = tid & 63, hg = tid >> 6;
    int l = blockIdx.x*64 + lg;
    const float* xb = x + (size_t)b*HH*LL + l;
    float s = 0.f, ss = 0.f;
    #pragma unroll 8
    for (int h = hg*64; h < hg*64 + 64; h++) {
        float v = xb[(size_t)h*LL] + tbs[h];
        s += v; ss = fmaf(v, v, ss);
    }
    sms[hg][lg] = s; smss[hg][lg] = ss;
    __syncthreads();
    float st  = sms[0][lg]  + sms[1][lg]  + sms[2][lg]  + sms[3][lg];
    float sst = smss[0][lg] + smss[1][lg] + smss[2][lg] + smss[3][lg];
    float mu  = st * (1.0f/HH);
    float var = sst*(1.0f/HH) - mu*mu;
    float rstd = rsqrtf(var + 1e-5f);
    float* zb = g_z + (size_t)b*HH*LL + l;
    #pragma unroll 8
    for (int h = hg*64; h < hg*64 + 64; h++) {
        float v = xb[(size_t)h*LL] + tbs[h];
        zb[(size_t)h*LL] = rtf((v - mu)*rstd*gs[h] + bs[h]);
    }
    // tail: feat -> tf32 pre-round
    {
        int gidx = (b*32 + blockIdx.x)*256 + tid;
        const float4* fs = (const float4*)feat;
        float4* fd = (float4*)g_ft;
        #pragma unroll
        for (int q = 0; q < 2; q++) {
            float4 v = fs[gidx*2 + q];
            v.x = rtf(v.x); v.y = rtf(v.y); v.z = rtf(v.z); v.w = rtf(v.w);
            fd[gidx*2 + q] = v;
        }
    }
}

// ---------------- chunked scan: one CTA per (h,dir), tf32 mma ----------------
#define GP 196
#define HP 68
#define VP 40
#define UP 40
#define CS_WORDS (64*GP + 128*HP + 192*VP + 128*UP)
#define CS_BYTES (CS_WORDS*4)

__global__ __launch_bounds__(256) void k_cscan(const float* __restrict__ Dv)
{
    extern __shared__ float sm[];
    float* Gs = sm;                 // 64 x GP
    float* Hs = Gs + 64*GP;         // 128 x HP
    float* V  = Hs + 128*HP;        // 192 x VP : [Z(64); S_re(64); S_im(64)] x 32b
    float* US = V  + 192*VP;        // 128 x UP
    __shared__ int s_tkt;

    const int hd = blockIdx.x, h = hd >> 1, dir = hd & 1;
    const int tid = threadIdx.x;
    const int w = tid >> 5, lane = tid & 31;
    const int gr = lane >> 2, tc = lane & 3;

    // load G, H into smem
    {
        const float4* gsrc = (const float4*)g_G[hd];
        for (int q = tid; q < 64*48; q += 256) {
            int row = q / 48, c4 = q % 48;
            *(float4*)&Gs[row*GP + c4*4] = gsrc[q];
        }
        const float4* hsrc = (const float4*)g_H[hd];
        for (int q = tid; q < 128*16; q += 256) {
            int row = q / 16, c4 = q % 16;
            *(float4*)&Hs[row*HP + c4*4] = hsrc[q];
        }
    }
    // zero state region of V
    for (int q = tid; q < 128*32; q += 256)
        V[(64 + (q >> 5))*VP + (q & 31)] = 0.f;

    // fp32 state registers: thread owns n = tid>>2, b = (tid&3)*8 .. +7
    const int sn = tid >> 2, sb0 = (tid & 3)*8;
    float s_re[8], s_im[8];
    #pragma unroll
    for (int k = 0; k < 8; k++) { s_re[k] = 0.f; s_im[k] = 0.f; }
    const float wtr = g_wTd[hd][sn], wti = g_wTd[hd][64 + sn];
    const float dD = dir ? Dv[h] : 0.f;

    // z chunk loading: thread (zb, jq) loads j = jq + 8t
    const int zb = tid >> 3, jq = tid & 7;
    const float* zbase = g_z + ((size_t)zb*HH + h)*LL;
    float* ybase = dir ? g_yb : g_yf;

    const int ch0 = dir ? (NCH - 1) : 0;
    const int stp = dir ? -1 : 1;
    {
        float zt[8];
        #pragma unroll
        for (int t = 0; t < 8; t++) zt[t] = zbase[ch0*TT + jq + 8*t];
        #pragma unroll
        for (int t = 0; t < 8; t++) V[(jq + 8*t)*VP + zb] = zt[t];
    }
    __syncthreads();

    for (int cc = 0; cc < NCH; cc++) {
        int c = ch0 + stp*cc;
        // prefetch next chunk's z into regs
        float zt[8];
        if (cc + 1 < NCH) {
            int cn = c + stp;
            #pragma unroll
            for (int t = 0; t < 8; t++) zt[t] = zbase[cn*TT + jq + 8*t];
        }

        if (w < 4) {
            // Y GEMM: rows w*16..+16, K=192, N=32
            float dY[4][4];
            #pragma unroll
            for (int ni = 0; ni < 4; ni++)
                #pragma unroll
                for (int q = 0; q < 4; q++) dY[ni][q] = 0.f;
            const float* Ab = Gs + (w*16 + gr)*GP + tc;
            #pragma unroll
            for (int kk = 0; kk < 24; kk++) {
                uint32_t a[4], bb[4][2];
                const float* ap = Ab + kk*8;
                a[0] = __float_as_uint(ap[0]);
                a[1] = __float_as_uint(ap[8*GP]);
                a[2] = __float_as_uint(ap[4]);
                a[3] = __float_as_uint(ap[8*GP + 4]);
                const float* bp = V + (kk*8 + tc)*VP + gr;
                #pragma unroll
                for (int ni = 0; ni < 4; ni++) {
                    bb[ni][0] = __float_as_uint(bp[ni*8]);
                    bb[ni][1] = __float_as_uint(bp[4*VP + ni*8]);
                }
                #pragma unroll
                for (int ni = 0; ni < 4; ni++) mma8(dY[ni], a, bb[ni]);
            }
            // write Y (+ D*z for bwd)
            int i0 = w*16 + gr;
            #pragma unroll
            for (int ni = 0; ni < 4; ni++) {
                int b0 = ni*8 + 2*tc;
                float v0 = dY[ni][0], v1 = dY[ni][1], v2 = dY[ni][2], v3 = dY[ni][3];
                if (dir) {
                    v0 = fmaf(dD, V[i0*VP + b0],       v0);
                    v1 = fmaf(dD, V[i0*VP + b0 + 1],   v1);
                    v2 = fmaf(dD, V[(i0+8)*VP + b0],   v2);
                    v3 = fmaf(dD, V[(i0+8)*VP + b0+1], v3);
                }
                size_t o0 = ((size_t)b0*HH + h)*LL + c*TT + i0;
                size_t o1 = ((size_t)(b0+1)*HH + h)*LL + c*TT + i0;
                ybase[o0]     = v0;
                ybase[o1]     = v1;
                ybase[o0 + 8] = v2;
                ybase[o1 + 8] = v3;
            }
        } else {
            // U GEMM: rows (w-4)*32..+32, K=64, N=32
            float dU[2][4][4];
            #pragma unroll
            for (int mi = 0; mi < 2; mi++)
                #pragma unroll
                for (int ni = 0; ni < 4; ni++)
                    #pragma unroll
                    for (int q = 0; q < 4; q++) dU[mi][ni][q] = 0.f;
            const int rb = (w - 4)*32;
            #pragma unroll
            for (int kk = 0; kk < 8; kk++) {
                uint32_t a[2][4], bb[4][2];
                #pragma unroll
                for (int mi = 0; mi < 2; mi++) {
                    const float* ap = Hs + (rb + mi*16 + gr)*HP + kk*8 + tc;
                    a[mi][0] = __float_as_uint(ap[0]);
                    a[mi][1] = __float_as_uint(ap[8*HP]);
                    a[mi][2] = __float_as_uint(ap[4]);
                    a[mi][3] = __float_as_uint(ap[8*HP + 4]);
                }
                const float* bp = V + (kk*8 + tc)*VP + gr;
                #pragma unroll
                for (int ni = 0; ni < 4; ni++) {
                    bb[ni][0] = __float_as_uint(bp[ni*8]);
                    bb[ni][1] = __float_as_uint(bp[4*VP + ni*8]);
                }
                #pragma unroll
                for (int mi = 0; mi < 2; mi++)
                    #pragma unroll
                    for (int ni = 0; ni < 4; ni++)
                        mma8(dU[mi][ni], a[mi], bb[ni]);
            }
            // stash U into smem
            #pragma unroll
            for (int mi = 0; mi < 2; mi++) {
                int r0 = rb + mi*16 + gr;
                #pragma unroll
                for (int ni = 0; ni < 4; ni++) {
                    int cb = ni*8 + 2*tc;
                    *(float2*)&US[r0*UP + cb]     = make_float2(dU[mi][ni][0], dU[mi][ni][1]);
                    *(float2*)&US[(r0+8)*UP + cb] = make_float2(dU[mi][ni][2], dU[mi][ni][3]);
                }
            }
        }
        __syncthreads();   // V reads + US writes complete

        // state update (fp32 regs), write tf32 copy into V; store next Z
        #pragma unroll
        for (int k = 0; k < 8; k++) {
            float ur = US[sn*UP + sb0 + k];
            float ui = US[(64 + sn)*UP + sb0 + k];
            float nr = fmaf(wtr, s_re[k], fmaf(-wti, s_im[k], ur));
            float ni_ = fmaf(wtr, s_im[k], fmaf(wti, s_re[k], ui));
            s_re[k] = nr; s_im[k] = ni_;
            V[(64 + sn)*VP + sb0 + k]  = rtf(nr);
            V[(128 + sn)*VP + sb0 + k] = rtf(ni_);
        }
        if (cc + 1 < NCH) {
            #pragma unroll
            for (int t = 0; t < 8; t++) V[(jq + 8*t)*VP + zb] = zt[t];
        }
        __syncthreads();
    }

    // ---- ticket: second (h) finisher applies gelu(yf+yb) over all 32 b-rows ----
    __threadfence();
    __syncthreads();
    if (tid == 0) s_tkt = atomicAdd(&g_cnt[h], 1);
    __syncthreads();
    if (s_tkt == 1) {
        __threadfence();
        for (int q = tid; q < 32*(LL/4); q += 256) {
            int b = q >> 9, off = q & 511;
            size_t base4 = ((size_t)b*HH + h)*(LL/4) + off;
            float4 a = ((const float4*)g_yf)[base4];
            float4 bv = ((const float4*)g_yb)[base4];
            float4 o;
            o.x = rtf(geluf(a.x + bv.x));
            o.y = rtf(geluf(a.y + bv.y));
            o.z = rtf(geluf(a.z + bv.z));
            o.w = rtf(geluf(a.w + bv.w));
            ((float4*)g_yf)[base4] = o;
        }
    }
}

// ================= tf32 tensor-core GEMM stages (cp.async double-buffered) =================
#define PW 36
#define PB 72
#define WS_SZ (128*PW)
#define BS_SZ (32*PB)
#define S1_WORDS (WS_SZ + BS_SZ)
#define S2_WORDS (2*WS_SZ + BS_SZ)
#define S1_BYTES (2*S1_WORDS*4)
#define S2_BYTES (2*S2_WORDS*4)

__device__ __forceinline__ void cpw_issue(uint32_t wA, const float* __restrict__ W,
                                          int g0, int k0, int sk, int tid)
{
    int g = tid >> 1, h0 = (tid & 1) * 16;
    const float* src = W + (size_t)(g0 + g)*sk + k0 + h0;
    uint32_t dst = wA + (uint32_t)(g*PW + h0)*4u;
    #pragma unroll
    for (int i = 0; i < 4; i++) cpa16(dst + 16u*i, src + 4*i);
}
__device__ __forceinline__ void cpb_issue(uint32_t bA, const float* __restrict__ Act,
                                          int k0, int l0, int tid)
{
    int hh = tid >> 3, lo = (tid & 7) * 8;
    const float* src = Act + (size_t)(k0 + hh)*LL + l0 + lo;
    uint32_t dst = bA + (uint32_t)(hh*PB + lo)*4u;
    cpa16(dst, src);
    cpa16(dst + 16u, src + 4);
}

__device__ __forceinline__ void mma_chunk(float d[2][4][4], const uint32_t* Ws, const uint32_t* Bsm,
                                          int wg, int wl, int gr, int tc)
{
    #pragma unroll
    for (int ks = 0; ks < 4; ks++) {
        int kk = ks*8;
        uint32_t a[2][4], bb[4][2];
        #pragma unroll
        for (int mi = 0; mi < 2; mi++) {
            const uint32_t* p = Ws + (wg + mi*16 + gr)*PW + kk + tc;
            a[mi][0] = p[0];
            a[mi][1] = p[8*PW];
            a[mi][2] = p[4];
            a[mi][3] = p[8*PW + 4];
        }
        #pragma unroll
        for (int ni = 0; ni < 4; ni++) {
            const uint32_t* p = Bsm + (kk + tc)*PB + wl + ni*8 + gr;
            bb[ni][0] = p[0];
            bb[ni][1] = p[4*PB];
        }
        #pragma unroll
        for (int mi = 0; mi < 2; mi++)
            #pragma unroll
            for (int ni = 0; ni < 4; ni++)
                mma8(d[mi][ni], a[mi], bb[ni]);
    }
}

// ---------------- stage1 ----------------
__global__ __launch_bounds__(256) void k_stage1(const float* __restrict__ bout,
                         const float* __restrict__ x, const float* __restrict__ bf)
{
    extern __shared__ uint32_t dsm[];
    const int b  = blockIdx.z;
    const int g0 = blockIdx.y * 128;
    const int l0 = blockIdx.x * 64;
    const int tid = threadIdx.x;
    const int w = tid >> 5, lane = tid & 31;
    const int wg = (w >> 1) * 32, wl = (w & 1) * 32;
    const int gr = lane >> 2, tc = lane & 3;

    uint32_t sb = (uint32_t)__cvta_generic_to_shared(dsm);
    uint32_t wA[2] = { sb, sb + (uint32_t)S1_WORDS*4u };
    uint32_t bA[2] = { sb + (uint32_t)WS_SZ*4u, sb + (uint32_t)(S1_WORDS + WS_SZ)*4u };

    float d[2][4][4];
    #pragma unroll
    for (int mi = 0; mi < 2; mi++)
        #pragma unroll
        for (int ni = 0; ni < 4; ni++)
            #pragma unroll
            for (int q = 0; q < 4; q++) d[mi][ni][q] = 0.f;

    const float* act = g_yf + (size_t)b*HH*LL;
    const float* ft  = g_ft + (size_t)b*FF*LL;

    cpw_issue(wA[0], g_WoutT, g0, 0, HH, tid);
    cpb_issue(bA[0], act, 0, l0, tid);
    cp_commit();

    for (int c = 0; c < 9; c++) {
        int cb = c & 1;
        if (c + 1 < 9) {
            int nb = cb ^ 1;
            if (c + 1 < 8) {
                cpw_issue(wA[nb], g_WoutT, g0, (c+1)*32, HH, tid);
                cpb_issue(bA[nb], act, (c+1)*32, l0, tid);
            } else {
                cpw_issue(wA[nb], g_WfT, g0, 0, FF, tid);
                cpb_issue(bA[nb], ft, 0, l0, tid);
            }
            cp_commit();
            cp_wait1();
        } else {
            cp_wait0();
        }
        __syncthreads();
        mma_chunk(d, dsm + cb*S1_WORDS, dsm + cb*S1_WORDS + WS_SZ, wg, wl, gr, tc);
        __syncthreads();
    }

    #pragma unroll
    for (int mi = 0; mi < 2; mi++) {
        int ga = g0 + wg + mi*16 + gr;
        int gb2 = ga + 8;
        float basea = bout[ga]  + bf[ga]  + g_tb[b*HH + ga];
        float baseb = bout[gb2] + bf[gb2] + g_tb[b*HH + gb2];
        #pragma unroll
        for (int ni = 0; ni < 4; ni++) {
            int l = l0 + wl + ni*8 + 2*tc;
            size_t offa = ((size_t)b*HH + ga)*LL + l;
            size_t offb = ((size_t)b*HH + gb2)*LL + l;
            float2 xa = *(const float2*)(x + offa);
            float2 xb = *(const float2*)(x + offb);
            float2 ra, rb;
            ra.x = rtf(gatef(d[mi][ni][0] + basea + xa.x));
            ra.y = rtf(gatef(d[mi][ni][1] + basea + xa.y));
            rb.x = rtf(gatef(d[mi][ni][2] + baseb + xb.x));
            rb.y = rtf(gatef(d[mi][ni][3] + baseb + xb.y));
            *(float2*)(g_z + offa) = ra;
            *(float2*)(g_z + offb) = rb;
        }
    }
}

// ---------------- stage2 ----------------
__global__ __launch_bounds__(256) void k_stage2(const float* __restrict__ b1,
                         const float* __restrict__ b2,
                         const float* __restrict__ x, float* __restrict__ o1,
                         float* __restrict__ o2)
{
    extern __shared__ uint32_t dsm[];
    const int b  = blockIdx.z;
    const int g0 = blockIdx.y * 128;
    const int l0 = blockIdx.x * 64;
    const int tid = threadIdx.x;
    const int w = tid >> 5, lane = tid & 31;
    const int wg = (w >> 1) * 32, wl = (w & 1) * 32;
    const int gr = lane >> 2, tc = lane & 3;

    uint32_t sb = (uint32_t)__cvta_generic_to_shared(dsm);
    uint32_t w1A[2] = { sb, sb + (uint32_t)S2_WORDS*4u };
    uint32_t w2A[2] = { sb + (uint32_t)WS_SZ*4u, sb + (uint32_t)(S2_WORDS + WS_SZ)*4u };
    uint32_t bA[2]  = { sb + (uint32_t)(2*WS_SZ)*4u, sb + (uint32_t)(S2_WORDS + 2*WS_SZ)*4u };

    float d1[2][4][4], d2[2][4][4];
    #pragma unroll
    for (int mi = 0; mi < 2; mi++)
        #pragma unroll
        for (int ni = 0; ni < 4; ni++)
            #pragma unroll
            for (int q = 0; q < 4; q++) { d1[mi][ni][q] = 0.f; d2[mi][ni][q] = 0.f; }

    const float* gb = g_z + (size_t)b*HH*LL;

    cpw_issue(w1A[0], g_W1T, g0, 0, HH, tid);
    cpw_issue(w2A[0], g_W2T, g0, 0, HH, tid);
    cpb_issue(bA[0], gb, 0, l0, tid);
    cp_commit();

    for (int c = 0; c < 8; c++) {
        int cb = c & 1;
        if (c + 1 < 8) {
            int nb = cb ^ 1;
            cpw_issue(w1A[nb], g_W1T, g0, (c+1)*32, HH, tid);
            cpw_issue(w2A[nb], g_W2T, g0, (c+1)*32, HH, tid);
            cpb_issue(bA[nb], gb, (c+1)*32, l0, tid);
            cp_commit();
            cp_wait1();
        } else {
            cp_wait0();
        }
        __syncthreads();
        const uint32_t* W1s = dsm + cb*S2_WORDS;
        const uint32_t* W2s = W1s + WS_SZ;
        const uint32_t* Bsm = W1s + 2*WS_SZ;
        #pragma unroll
        for (int ks = 0; ks < 4; ks++) {
            int kk = ks*8;
            uint32_t a1[2][4], a2[2][4], bb[4][2];
            #pragma unroll
            for (int mi = 0; mi < 2; mi++) {
                const uint32_t* p1 = W1s + (wg + mi*16 + gr)*PW + kk + tc;
                a1[mi][0] = p1[0]; a1[mi][1] = p1[8*PW]; a1[mi][2] = p1[4]; a1[mi][3] = p1[8*PW + 4];
                const uint32_t* p2 = W2s + (wg + mi*16 + gr)*PW + kk + tc;
                a2[mi][0] = p2[0]; a2[mi][1] = p2[8*PW]; a2[mi][2] = p2[4]; a2[mi][3] = p2[8*PW + 4];
            }
            #pragma unroll
            for (int ni = 0; ni < 4; ni++) {
                const uint32_t* p = Bsm + (kk + tc)*PB + wl + ni*8 + gr;
                bb[ni][0] = p[0];
                bb[ni][1] = p[4*PB];
            }
            #pragma unroll
            for (int mi = 0; mi < 2; mi++)
                #pragma unroll
                for (int ni = 0; ni < 4; ni++) {
                    mma8(d1[mi][ni], a1[mi], bb[ni]);
                    mma8(d2[mi][ni], a2[mi], bb[ni]);
                }
        }
        __syncthreads();
    }

    #pragma unroll
    for (int mi = 0; mi < 2; mi++) {
        int ga = g0 + wg + mi*16 + gr;
        int gb2 = ga + 8;
        float b1a = b1[ga], b1b = b1[gb2];
        float b2a = b2[ga], b2b = b2[gb2];
        #pragma unroll
        for (int ni = 0; ni < 4; ni++) {
            int l = l0 + wl + ni*8 + 2*tc;
            size_t offa = ((size_t)b*HH + ga)*LL + l;
            size_t offb = ((size_t)b*HH + gb2)*LL + l;
            float2 xa = *(const float2*)(x + offa);
            float2 xb = *(const float2*)(x + offb);
            float2 r;
            r.x = d1[mi][ni][0] + b1a + xa.x;
            r.y = d1[mi][ni][1] + b1a + xa.y;
            *(float2*)(o1 + offa) = r;
            r.x = d1[mi][ni][2] + b1b + xb.x;
            r.y = d1[mi][ni][3] + b1b + xb.y;
            *(float2*)(o1 + offb) = r;
            r.x = d2[mi][ni][0] + b2a;
            r.y = d2[mi][ni][1] + b2a;
            *(float2*)(o2 + offa) = r;
            r.x = d2[mi][ni][2] + b2b;
            r.y = d2[mi][ni][3] + b2b;
            *(float2*)(o2 + offb) = r;
        }
    }
}

// ---------------- launch ----------------
extern "C" void kernel_launch(void* const* d_in, const int* in_sizes, int n_in,
                              void* d_out, int out_size)
{
    const float* x        = (const float*)d_in[0];
    const float* t        = (const float*)d_in[1];
    const float* feat     = (const float*)d_in[2];
    const float* Wt       = (const float*)d_in[3];
    const float* bt       = (const float*)d_in[4];
    const float* ln_g     = (const float*)d_in[5];
    const float* ln_b     = (const float*)d_in[6];
    const float* log_dt   = (const float*)d_in[7];
    const float* logA_real= (const float*)d_in[8];
    const float* A_imag   = (const float*)d_in[9];
    const float* C_re     = (const float*)d_in[10];
    const float* C_im     = (const float*)d_in[11];
    const float* Dv       = (const float*)d_in[12];
    const float* Wout     = (const float*)d_in[13];
    const float* bout     = (const float*)d_in[14];
    const float* W1       = (const float*)d_in[15];
    const float* b1       = (const float*)d_in[16];
    const float* W2       = (const float*)d_in[17];
    const float* b2       = (const float*)d_in[18];
    const float* Wf       = (const float*)d_in[19];
    const float* bf       = (const float*)d_in[20];

    float* o1 = (float*)d_out;
    float* o2 = (float*)d_out + (size_t)BHL;

    cudaFuncSetAttribute(k_cscan, cudaFuncAttributeMaxDynamicSharedMemorySize, CS_BYTES);
    cudaFuncSetAttribute(k_stage1, cudaFuncAttributeMaxDynamicSharedMemorySize, S1_BYTES);
    cudaFuncSetAttribute(k_stage2, cudaFuncAttributeMaxDynamicSharedMemorySize, S2_BYTES);

    k_cvtw<<<(HH*HH)/256, 256>>>(Wout, W1, W2, Wf);
    k_tb<<<dim3(4, BB), 256>>>(t, Wt, bt);
    k_prep<<<2*HH, 256>>>(log_dt, logA_real, A_imag, C_re, C_im);
    k_ln<<<dim3(LL/64, BB), 256>>>(x, ln_g, ln_b, feat);
    k_cscan<<<2*HH, 256, CS_BYTES>>>(Dv);
    k_stage1<<<dim3(LL/64, HH/128, BB), 256, S1_BYTES>>>(bout, x, bf);
    k_stage2<<<dim3(LL/64, HH/128, BB), 256, S2_BYTES>>>(b1, b2, x, o1, o2);
}